// round 6
// baseline (speedup 1.0000x reference)
#include <cuda_runtime.h>
#include <cstdint>

// Problem constants (fixed by the dataset)
#define P_N 100000
#define P_D 64
#define P_H 128
#define P_O 64

// Scratch: __device__ globals, only ever touched from device code.
__device__ float s_agA[P_N * P_D];   // layer-1 neighbor sums   (25.6 MB)
__device__ float s_cnt[P_N];         // in-degree               (0.4 MB)
__device__ float s_t1 [P_N * P_H];   // h1                      (51.2 MB)
__device__ float s_t2 [P_N * P_H];   // h2                      (51.2 MB)
__device__ float s_agB[P_N * P_H];   // layer-2 neighbor sums   (51.2 MB)
__device__ float s_t3 [P_N * P_H];   // h3                      (51.2 MB)

// ---------------------------------------------------------------------------
// Zero scratch accumulators (vector grid-stride).
// ---------------------------------------------------------------------------
__global__ void kz_fill(int dummy) {
    const float4 z = make_float4(0.f, 0.f, 0.f, 0.f);
    int idx = blockIdx.x * blockDim.x + threadIdx.x;
    int stride = gridDim.x * blockDim.x;
    for (int i = idx; i < P_N * P_D / 4; i += stride)
        reinterpret_cast<float4*>(s_agA)[i] = z;
    for (int i = idx; i < P_N * P_H / 4; i += stride)
        reinterpret_cast<float4*>(s_agB)[i] = z;
    for (int i = idx; i < P_N; i += stride)
        s_cnt[i] = 0.0f;
}

// ---------------------------------------------------------------------------
// Edge scatter, layer 1: s_agA[dst*64 + 4c..] += x[src*64 + 4c..]
// edge_index is INT32 (JAX x64 disabled): ei[0..E-1]=src, ei[E..2E-1]=dst.
// One thread per (edge, float4-chunk): 16 chunks/edge.
// ---------------------------------------------------------------------------
__global__ void ksc_one(const float4* __restrict__ x4,
                        const int* __restrict__ ei, int E) {
    int idx = blockIdx.x * blockDim.x + threadIdx.x;
    if (idx >= E * 16) return;
    int e = idx >> 4;
    int c = idx & 15;
    int src = ei[e];
    int dst = ei[E + e];
    float4 v = x4[src * 16 + c];
    float* p = s_agA + dst * 64 + c * 4;
    atomicAdd(p + 0, v.x);
    atomicAdd(p + 1, v.y);
    atomicAdd(p + 2, v.z);
    atomicAdd(p + 3, v.w);
    if (c == 0) atomicAdd(&s_cnt[dst], 1.0f);
}

// ---------------------------------------------------------------------------
// Edge scatter, layer 2: s_agB[dst*128 + 4c..] += s_t2[src*128 + 4c..]
// 32 chunks/edge.
// ---------------------------------------------------------------------------
__global__ void ksc_two(const int* __restrict__ ei, int E) {
    long long idx = (long long)blockIdx.x * blockDim.x + threadIdx.x;
    if (idx >= (long long)E * 32) return;
    int e = (int)(idx >> 5);
    int c = (int)(idx & 31);
    int src = ei[e];
    int dst = ei[E + e];
    const float4* h2v = reinterpret_cast<const float4*>(s_t2);
    float4 v = h2v[src * 32 + c];
    float* p = s_agB + dst * 128 + c * 4;
    atomicAdd(p + 0, v.x);
    atomicAdd(p + 1, v.y);
    atomicAdd(p + 2, v.z);
    atomicAdd(p + 3, v.w);
}

// ---------------------------------------------------------------------------
// Shared GEMM body: C = act( scale(A1) @ W1 [+ A2 @ W2] + bias )
// A1:[n,K1] (scaled by 1/max(deg,1) if SC), A2:[n,K2], W:[K,HO] row-major.
// blockDim.x == HO. 32 rows per block. K tiled by 64.
// ---------------------------------------------------------------------------
template<int K1, int K2, int HO, bool RELU, bool SC>
__device__ __forceinline__ void mm_body(const float* A1, const float* A2,
                                        const float* W1, const float* W2,
                                        const float* bias, float* C,
                                        const float* deg, int n) {
    constexpr int ROWS = 32;
    constexpr int KTOT = K1 + K2;
    constexpr int KT   = 64;
    constexpr int AS   = ROWS + 4;   // 36 floats = 144 B: 16B-aligned rows, pad vs conflicts

    __shared__ __align__(16) float shA[KT * AS];
    __shared__ __align__(16) float shW[KT * HO];
    __shared__ float shS[ROWS];

    const int col  = threadIdx.x;    // 0..HO-1
    const int row0 = blockIdx.x * ROWS;

    if (SC) {
        if (threadIdx.x < ROWS) {
            int gr = row0 + threadIdx.x;
            float d = (gr < n) ? deg[gr] : 1.0f;
            shS[threadIdx.x] = 1.0f / fmaxf(d, 1.0f);
        }
        __syncthreads();
    }

    float acc[ROWS];
#pragma unroll
    for (int r = 0; r < ROWS; ++r) acc[r] = 0.0f;

    for (int kt = 0; kt < KTOT; kt += KT) {
        // W tile (KT x HO), float4 coalesced
        const float* Wsrc = (kt < K1) ? (W1 + kt * HO) : (W2 + (kt - K1) * HO);
        for (int i = threadIdx.x * 4; i < KT * HO; i += blockDim.x * 4)
            *reinterpret_cast<float4*>(&shW[i]) =
                *reinterpret_cast<const float4*>(&Wsrc[i]);

        // A tile transposed: shA[k*AS + r]
        const float* Asrc;
        int kbase, KA;
        if (kt < K1) { Asrc = A1; kbase = kt;      KA = K1; }
        else         { Asrc = A2; kbase = kt - K1; KA = (K2 > 0) ? K2 : 1; }
        for (int i = threadIdx.x; i < ROWS * KT; i += blockDim.x) {
            int r  = i / KT;
            int lk = i - r * KT;
            int gr = row0 + r;
            float v = (gr < n) ? Asrc[gr * KA + kbase + lk] : 0.0f;
            if (SC && kt < K1) v *= shS[r];
            shA[lk * AS + r] = v;
        }
        __syncthreads();

        // inner: FFMA-bound, A rows read as float4 broadcasts
#pragma unroll 4
        for (int k = 0; k < KT; ++k) {
            float w = shW[k * HO + col];
            const float4* ap = reinterpret_cast<const float4*>(&shA[k * AS]);
#pragma unroll
            for (int r4 = 0; r4 < ROWS / 4; ++r4) {
                float4 a = ap[r4];
                acc[r4 * 4 + 0] = fmaf(a.x, w, acc[r4 * 4 + 0]);
                acc[r4 * 4 + 1] = fmaf(a.y, w, acc[r4 * 4 + 1]);
                acc[r4 * 4 + 2] = fmaf(a.z, w, acc[r4 * 4 + 2]);
                acc[r4 * 4 + 3] = fmaf(a.w, w, acc[r4 * 4 + 3]);
            }
        }
        __syncthreads();
    }

    float b = bias[col];
#pragma unroll
    for (int r = 0; r < ROWS; ++r) {
        int gr = row0 + r;
        if (gr < n) {
            float v = acc[r] + b;
            if (RELU) v = fmaxf(v, 0.0f);
            C[gr * HO + col] = v;
        }
    }
}

// Plain wrapper kernels referencing the device globals directly.
__global__ void kmm_one(const float* __restrict__ xin,
                        const float* __restrict__ W1l,
                        const float* __restrict__ W1r,
                        const float* __restrict__ b1, int n) {
    mm_body<64, 64, 128, true, true>(s_agA, xin, W1l, W1r, b1, s_t1, s_cnt, n);
}
__global__ void kmm_two(const float* __restrict__ Wlin1,
                        const float* __restrict__ blin1, int n) {
    mm_body<128, 0, 128, true, false>(s_t1, nullptr, Wlin1, nullptr, blin1, s_t2, s_cnt, n);
}
__global__ void kmm_three(const float* __restrict__ W2l,
                          const float* __restrict__ W2r,
                          const float* __restrict__ b2, int n) {
    mm_body<128, 128, 128, true, true>(s_agB, s_t2, W2l, W2r, b2, s_t3, s_cnt, n);
}
__global__ void kmm_four(const float* __restrict__ Wlin2,
                         const float* __restrict__ blin2,
                         float* __restrict__ outp, int n) {
    mm_body<128, 0, 64, false, false>(s_t3, nullptr, Wlin2, nullptr, blin2, outp, s_cnt, n);
}

// ---------------------------------------------------------------------------
// Launch. Inputs (metadata order): x, edge_index, W1l, b1, W1r, Wlin1, blin1,
//                                  W2l, b2, W2r, Wlin2, blin2
// edge_index: int32 [2, E] (JAX x64 disabled => int64 request yields int32).
// ---------------------------------------------------------------------------
extern "C" void kernel_launch(void* const* d_in, const int* in_sizes, int n_in,
                              void* d_out, int out_size) {
    const float* xin   = (const float*)d_in[0];
    const int*   eidx  = (const int*)d_in[1];
    const float* W1l   = (const float*)d_in[2];
    const float* b1    = (const float*)d_in[3];
    const float* W1r   = (const float*)d_in[4];
    const float* Wlin1 = (const float*)d_in[5];
    const float* blin1 = (const float*)d_in[6];
    const float* W2l   = (const float*)d_in[7];
    const float* b2    = (const float*)d_in[8];
    const float* W2r   = (const float*)d_in[9];
    const float* Wlin2 = (const float*)d_in[10];
    const float* blin2 = (const float*)d_in[11];
    float*       outp  = (float*)d_out;

    const int n = in_sizes[0] / P_D;   // 100000
    const int E = in_sizes[1] / 2;     // 1600000

    kz_fill<<<1184, 256>>>(0);

    const int nblk = (n + 31) / 32;

    // Layer 1 aggregation (+ degree): E*16 threads
    ksc_one<<<(E * 16 + 255) / 256, 256>>>(
        reinterpret_cast<const float4*>(xin), eidx, E);

    kmm_one<<<nblk, 128>>>(xin, W1l, W1r, b1, n);
    kmm_two<<<nblk, 128>>>(Wlin1, blin1, n);

    // Layer 2 aggregation: E*32 threads
    {
        long long tot = (long long)E * 32;
        int grid = (int)((tot + 255) / 256);
        ksc_two<<<grid, 256>>>(eidx, E);
    }

    kmm_three<<<nblk, 128>>>(W2l, W2r, b2, n);
    kmm_four<<<nblk, 64>>>(Wlin2, blin2, outp, n);
}

// round 7
// speedup vs baseline: 1.1627x; 1.1627x over previous
#include <cuda_runtime.h>
#include <cstdint>

// Problem constants (fixed by the dataset)
#define P_N 100000
#define P_D 64
#define P_H 128
#define P_O 64

// Scratch: __device__ globals, only ever touched from device code.
__device__ float s_agA[P_N * P_D];   // layer-1 neighbor sums   (25.6 MB)
__device__ float s_cnt[P_N];         // in-degree               (0.4 MB)
__device__ float s_t1 [P_N * P_H];   // h1                      (51.2 MB)
__device__ float s_t2 [P_N * P_H];   // h2                      (51.2 MB)
__device__ float s_agB[P_N * P_H];   // layer-2 neighbor sums   (51.2 MB)
__device__ float s_t3 [P_N * P_H];   // h3                      (51.2 MB)

// ---------------------------------------------------------------------------
// Zero scratch accumulators (vector grid-stride).
// ---------------------------------------------------------------------------
__global__ void kz_fill(int dummy) {
    const float4 z = make_float4(0.f, 0.f, 0.f, 0.f);
    int idx = blockIdx.x * blockDim.x + threadIdx.x;
    int stride = gridDim.x * blockDim.x;
    for (int i = idx; i < P_N * P_D / 4; i += stride)
        reinterpret_cast<float4*>(s_agA)[i] = z;
    for (int i = idx; i < P_N * P_H / 4; i += stride)
        reinterpret_cast<float4*>(s_agB)[i] = z;
    for (int i = idx; i < P_N; i += stride)
        s_cnt[i] = 0.0f;
}

// ---------------------------------------------------------------------------
// Edge scatter, layer 1: s_agA[dst*64 + 4c..] += x[src*64 + 4c..]
// edge_index is INT32: ei[0..E-1]=src, ei[E..2E-1]=dst. 16 chunks/edge.
// ---------------------------------------------------------------------------
__global__ void ksc_one(const float4* __restrict__ x4,
                        const int* __restrict__ ei, int E) {
    int idx = blockIdx.x * blockDim.x + threadIdx.x;
    if (idx >= E * 16) return;
    int e = idx >> 4;
    int c = idx & 15;
    int src = ei[e];
    int dst = ei[E + e];
    float4 v = x4[src * 16 + c];
    float* p = s_agA + dst * 64 + c * 4;
    atomicAdd(p + 0, v.x);
    atomicAdd(p + 1, v.y);
    atomicAdd(p + 2, v.z);
    atomicAdd(p + 3, v.w);
    if (c == 0) atomicAdd(&s_cnt[dst], 1.0f);
}

// ---------------------------------------------------------------------------
// Edge scatter, layer 2: s_agB[dst*128 + 4c..] += s_t2[src*128 + 4c..]
// 32 chunks/edge.
// ---------------------------------------------------------------------------
__global__ void ksc_two(const int* __restrict__ ei, int E) {
    long long idx = (long long)blockIdx.x * blockDim.x + threadIdx.x;
    if (idx >= (long long)E * 32) return;
    int e = (int)(idx >> 5);
    int c = (int)(idx & 31);
    int src = ei[e];
    int dst = ei[E + e];
    const float4* h2v = reinterpret_cast<const float4*>(s_t2);
    float4 v = h2v[src * 32 + c];
    float* p = s_agB + dst * 128 + c * 4;
    atomicAdd(p + 0, v.x);
    atomicAdd(p + 1, v.y);
    atomicAdd(p + 2, v.z);
    atomicAdd(p + 3, v.w);
}

// ---------------------------------------------------------------------------
// Register-blocked GEMM body: C = act( scale(A1) @ W1 [+ A2 @ W2] + bias )
// Tile: 64 rows x HO cols per block; each thread owns 8 rows x 4 cols.
// Threads: (HO/4) x 8. Per k-step per thread: 2 broadcast LDS.128 (A) +
// 1 LDS.128 (W) feeding 32 FFMAs -> FMA-issue-bound.
// ---------------------------------------------------------------------------
template<int K1, int K2, int HO, bool RELU, bool SC>
__device__ __forceinline__ void mm_body(const float* A1, const float* A2,
                                        const float* W1, const float* W2,
                                        const float* bias, float* C,
                                        const float* deg, int n) {
    constexpr int MT   = 64;          // rows per block
    constexpr int KT   = 32;          // k tile
    constexpr int KTOT = K1 + K2;
    constexpr int AS   = MT + 4;      // 68: row stride, 16B-aligned (68*4=272)
    constexpr int NTHR = (HO / 4) * 8;

    __shared__ __align__(16) float shA[KT * AS];      // A^T tile
    __shared__ __align__(16) float shW[KT * HO];      // W tile
    __shared__ float shS[MT];

    const int tid  = threadIdx.x;
    const int tx   = tid % (HO / 4);  // col group: cols tx*4 .. tx*4+3
    const int ty   = tid / (HO / 4);  // row group: rows ty*8 .. ty*8+7
    const int row0 = blockIdx.x * MT;

    if (SC) {
        if (tid < MT) {
            int gr = row0 + tid;
            float d = (gr < n) ? deg[gr] : 1.0f;
            shS[tid] = 1.0f / fmaxf(d, 1.0f);
        }
        __syncthreads();
    }

    float acc[8][4];
#pragma unroll
    for (int r = 0; r < 8; ++r)
#pragma unroll
        for (int c = 0; c < 4; ++c) acc[r][c] = 0.0f;

    for (int kt = 0; kt < KTOT; kt += KT) {
        // --- W tile (KT x HO), float4 coalesced ---
        const float* Wsrc = (kt < K1) ? (W1 + kt * HO) : (W2 + (kt - K1) * HO);
#pragma unroll
        for (int i = tid * 4; i < KT * HO; i += NTHR * 4)
            *reinterpret_cast<float4*>(&shW[i]) =
                *reinterpret_cast<const float4*>(&Wsrc[i]);

        // --- A tile transposed: shA[lk*AS + r] ---
        const float* Asrc;
        int kbase, KA;
        if (kt < K1) { Asrc = A1; kbase = kt;      KA = K1; }
        else         { Asrc = A2; kbase = kt - K1; KA = (K2 > 0) ? K2 : 1; }
#pragma unroll
        for (int i = tid; i < MT * KT; i += NTHR) {
            int r  = i / KT;
            int lk = i - r * KT;
            int gr = row0 + r;
            float v = (gr < n) ? Asrc[gr * KA + kbase + lk] : 0.0f;
            if (SC && kt < K1) v *= shS[r];
            shA[lk * AS + r] = v;
        }
        __syncthreads();

#pragma unroll 4
        for (int k = 0; k < KT; ++k) {
            float4 w  = *reinterpret_cast<const float4*>(&shW[k * HO + tx * 4]);
            float4 a0 = *reinterpret_cast<const float4*>(&shA[k * AS + ty * 8]);
            float4 a1 = *reinterpret_cast<const float4*>(&shA[k * AS + ty * 8 + 4]);
            float av[8] = {a0.x, a0.y, a0.z, a0.w, a1.x, a1.y, a1.z, a1.w};
#pragma unroll
            for (int r = 0; r < 8; ++r) {
                acc[r][0] = fmaf(av[r], w.x, acc[r][0]);
                acc[r][1] = fmaf(av[r], w.y, acc[r][1]);
                acc[r][2] = fmaf(av[r], w.z, acc[r][2]);
                acc[r][3] = fmaf(av[r], w.w, acc[r][3]);
            }
        }
        __syncthreads();
    }

    float4 b = *reinterpret_cast<const float4*>(&bias[tx * 4]);
#pragma unroll
    for (int r = 0; r < 8; ++r) {
        int gr = row0 + ty * 8 + r;
        if (gr < n) {
            float4 o;
            o.x = acc[r][0] + b.x;
            o.y = acc[r][1] + b.y;
            o.z = acc[r][2] + b.z;
            o.w = acc[r][3] + b.w;
            if (RELU) {
                o.x = fmaxf(o.x, 0.0f); o.y = fmaxf(o.y, 0.0f);
                o.z = fmaxf(o.z, 0.0f); o.w = fmaxf(o.w, 0.0f);
            }
            *reinterpret_cast<float4*>(&C[gr * HO + tx * 4]) = o;
        }
    }
}

// Plain wrapper kernels referencing the device globals directly.
__global__ void kmm_one(const float* __restrict__ xin,
                        const float* __restrict__ W1l,
                        const float* __restrict__ W1r,
                        const float* __restrict__ b1, int n) {
    mm_body<64, 64, 128, true, true>(s_agA, xin, W1l, W1r, b1, s_t1, s_cnt, n);
}
__global__ void kmm_two(const float* __restrict__ Wlin1,
                        const float* __restrict__ blin1, int n) {
    mm_body<128, 0, 128, true, false>(s_t1, nullptr, Wlin1, nullptr, blin1, s_t2, s_cnt, n);
}
__global__ void kmm_three(const float* __restrict__ W2l,
                          const float* __restrict__ W2r,
                          const float* __restrict__ b2, int n) {
    mm_body<128, 128, 128, true, true>(s_agB, s_t2, W2l, W2r, b2, s_t3, s_cnt, n);
}
__global__ void kmm_four(const float* __restrict__ Wlin2,
                         const float* __restrict__ blin2,
                         float* __restrict__ outp, int n) {
    mm_body<128, 0, 64, false, false>(s_t3, nullptr, Wlin2, nullptr, blin2, outp, s_cnt, n);
}

// ---------------------------------------------------------------------------
// Launch. Inputs (metadata order): x, edge_index, W1l, b1, W1r, Wlin1, blin1,
//                                  W2l, b2, W2r, Wlin2, blin2
// ---------------------------------------------------------------------------
extern "C" void kernel_launch(void* const* d_in, const int* in_sizes, int n_in,
                              void* d_out, int out_size) {
    const float* xin   = (const float*)d_in[0];
    const int*   eidx  = (const int*)d_in[1];
    const float* W1l   = (const float*)d_in[2];
    const float* b1    = (const float*)d_in[3];
    const float* W1r   = (const float*)d_in[4];
    const float* Wlin1 = (const float*)d_in[5];
    const float* blin1 = (const float*)d_in[6];
    const float* W2l   = (const float*)d_in[7];
    const float* b2    = (const float*)d_in[8];
    const float* W2r   = (const float*)d_in[9];
    const float* Wlin2 = (const float*)d_in[10];
    const float* blin2 = (const float*)d_in[11];
    float*       outp  = (float*)d_out;

    const int n = in_sizes[0] / P_D;   // 100000
    const int E = in_sizes[1] / 2;     // 1600000

    kz_fill<<<1184, 256>>>(0);

    const int nblk = (n + 63) / 64;    // 64 rows per block

    // Layer 1 aggregation (+ degree): E*16 threads
    ksc_one<<<(E * 16 + 255) / 256, 256>>>(
        reinterpret_cast<const float4*>(xin), eidx, E);

    kmm_one<<<nblk, 256>>>(xin, W1l, W1r, b1, n);
    kmm_two<<<nblk, 256>>>(Wlin1, blin1, n);

    // Layer 2 aggregation: E*32 threads
    {
        long long tot = (long long)E * 32;
        int grid = (int)((tot + 255) / 256);
        ksc_two<<<grid, 256>>>(eidx, E);
    }

    kmm_three<<<nblk, 256>>>(W2l, W2r, b2, n);
    kmm_four<<<nblk, 128>>>(Wlin2, blin2, outp, n);
}

// round 8
// speedup vs baseline: 1.6217x; 1.3948x over previous
#include <cuda_runtime.h>
#include <cstdint>

// Problem constants (fixed by the dataset)
#define P_N 100000
#define P_D 64
#define P_H 128
#define P_O 64

// Scratch: __device__ globals, only ever touched from device code.
__device__ float s_agA[P_N * P_D];   // layer-1 neighbor sums   (25.6 MB)
__device__ float s_cnt[P_N];         // in-degree               (0.4 MB)
__device__ float s_t1 [P_N * P_H];   // h1                      (51.2 MB)
__device__ float s_t2 [P_N * P_H];   // h2                      (51.2 MB)
__device__ float s_agB[P_N * P_H];   // layer-2 neighbor sums   (51.2 MB)
__device__ float s_t3 [P_N * P_H];   // h3                      (51.2 MB)

__device__ __forceinline__ void red_add_v4(float* p, float4 v) {
    asm volatile("red.global.add.v4.f32 [%0], {%1, %2, %3, %4};"
                 :: "l"(p), "f"(v.x), "f"(v.y), "f"(v.z), "f"(v.w)
                 : "memory");
}

// ---------------------------------------------------------------------------
// Zero scratch accumulators (vector grid-stride).
// ---------------------------------------------------------------------------
__global__ void kz_fill(int dummy) {
    const float4 z = make_float4(0.f, 0.f, 0.f, 0.f);
    int idx = blockIdx.x * blockDim.x + threadIdx.x;
    int stride = gridDim.x * blockDim.x;
    for (int i = idx; i < P_N * P_D / 4; i += stride)
        reinterpret_cast<float4*>(s_agA)[i] = z;
    for (int i = idx; i < P_N * P_H / 4; i += stride)
        reinterpret_cast<float4*>(s_agB)[i] = z;
    for (int i = idx; i < P_N; i += stride)
        s_cnt[i] = 0.0f;
}

// ---------------------------------------------------------------------------
// Edge scatter, layer 1: s_agA[dst*64 + 4c..] += x[src*64 + 4c..]
// edge_index is INT32: ei[0..E-1]=src, ei[E..2E-1]=dst. 16 chunks/edge.
// Vector reduction: 1 RED.128 per chunk instead of 4 scalar REDs.
// ---------------------------------------------------------------------------
__global__ void ksc_one(const float4* __restrict__ x4,
                        const int* __restrict__ ei, int E) {
    int idx = blockIdx.x * blockDim.x + threadIdx.x;
    if (idx >= E * 16) return;
    int e = idx >> 4;
    int c = idx & 15;
    int src = ei[e];
    int dst = ei[E + e];
    float4 v = x4[src * 16 + c];
    red_add_v4(s_agA + dst * 64 + c * 4, v);
    if (c == 0) atomicAdd(&s_cnt[dst], 1.0f);
}

// ---------------------------------------------------------------------------
// Edge scatter, layer 2: s_agB[dst*128 + 4c..] += s_t2[src*128 + 4c..]
// 32 chunks/edge.
// ---------------------------------------------------------------------------
__global__ void ksc_two(const int* __restrict__ ei, int E) {
    long long idx = (long long)blockIdx.x * blockDim.x + threadIdx.x;
    if (idx >= (long long)E * 32) return;
    int e = (int)(idx >> 5);
    int c = (int)(idx & 31);
    int src = ei[e];
    int dst = ei[E + e];
    const float4* h2v = reinterpret_cast<const float4*>(s_t2);
    float4 v = h2v[src * 32 + c];
    red_add_v4(s_agB + dst * 128 + c * 4, v);
}

// ---------------------------------------------------------------------------
// Register-blocked GEMM: C = act( scale(A1) @ W1 [+ A2 @ W2] + bias )
// Tile: MT=128 rows x HO cols per block; each thread owns 8 rows x 8 cols.
// Per k-step per thread: 2 broadcast LDS.128 (A) + 2 LDS.128 (W) -> 64 FFMA.
// ---------------------------------------------------------------------------
template<int K1, int K2, int HO, bool RELU, bool SC>
__device__ __forceinline__ void mm_body(const float* A1, const float* A2,
                                        const float* W1, const float* W2,
                                        const float* bias, float* C,
                                        const float* deg, int n) {
    constexpr int MT   = 128;         // rows per block
    constexpr int KT   = 32;          // k tile
    constexpr int KTOT = K1 + K2;
    constexpr int AS   = MT + 4;      // 132: row stride, 16B-aligned
    constexpr int NTHR = (HO / 8) * (MT / 8);

    __shared__ __align__(16) float shA[KT * AS];      // A^T tile (16.9 KB)
    __shared__ __align__(16) float shW[KT * HO];      // W tile   (16 KB max)
    __shared__ float shS[MT];

    const int tid  = threadIdx.x;
    const int tx   = tid % (HO / 8);  // col group: cols tx*8 .. tx*8+7
    const int ty   = tid / (HO / 8);  // row group: rows ty*8 .. ty*8+7
    const int row0 = blockIdx.x * MT;

    if (SC) {
        for (int i = tid; i < MT; i += NTHR) {
            int gr = row0 + i;
            float d = (gr < n) ? deg[gr] : 1.0f;
            shS[i] = 1.0f / fmaxf(d, 1.0f);
        }
        __syncthreads();
    }

    float acc[8][8];
#pragma unroll
    for (int r = 0; r < 8; ++r)
#pragma unroll
        for (int c = 0; c < 8; ++c) acc[r][c] = 0.0f;

    for (int kt = 0; kt < KTOT; kt += KT) {
        // --- W tile (KT x HO), float4 coalesced ---
        const float* Wsrc = (kt < K1) ? (W1 + kt * HO) : (W2 + (kt - K1) * HO);
#pragma unroll
        for (int i = tid * 4; i < KT * HO; i += NTHR * 4)
            *reinterpret_cast<float4*>(&shW[i]) =
                *reinterpret_cast<const float4*>(&Wsrc[i]);

        // --- A tile transposed: float4 global loads, scalar transposed STS ---
        const float* Asrc;
        int kbase, KA;
        if (kt < K1) { Asrc = A1; kbase = kt;      KA = K1; }
        else         { Asrc = A2; kbase = kt - K1; KA = (K2 > 0) ? K2 : 1; }
#pragma unroll
        for (int i = tid; i < MT * (KT / 4); i += NTHR) {
            int r   = i / (KT / 4);
            int lk4 = i - r * (KT / 4);
            int gr  = row0 + r;
            float4 v = make_float4(0.f, 0.f, 0.f, 0.f);
            if (gr < n)
                v = *reinterpret_cast<const float4*>(&Asrc[gr * KA + kbase + lk4 * 4]);
            if (SC && kt < K1) {
                float s = shS[r];
                v.x *= s; v.y *= s; v.z *= s; v.w *= s;
            }
            shA[(lk4 * 4 + 0) * AS + r] = v.x;
            shA[(lk4 * 4 + 1) * AS + r] = v.y;
            shA[(lk4 * 4 + 2) * AS + r] = v.z;
            shA[(lk4 * 4 + 3) * AS + r] = v.w;
        }
        __syncthreads();

#pragma unroll 2
        for (int k = 0; k < KT; ++k) {
            float4 w0 = *reinterpret_cast<const float4*>(&shW[k * HO + tx * 8]);
            float4 w1 = *reinterpret_cast<const float4*>(&shW[k * HO + tx * 8 + 4]);
            float4 a0 = *reinterpret_cast<const float4*>(&shA[k * AS + ty * 8]);
            float4 a1 = *reinterpret_cast<const float4*>(&shA[k * AS + ty * 8 + 4]);
            float av[8] = {a0.x, a0.y, a0.z, a0.w, a1.x, a1.y, a1.z, a1.w};
            float wv[8] = {w0.x, w0.y, w0.z, w0.w, w1.x, w1.y, w1.z, w1.w};
#pragma unroll
            for (int r = 0; r < 8; ++r)
#pragma unroll
                for (int c = 0; c < 8; ++c)
                    acc[r][c] = fmaf(av[r], wv[c], acc[r][c]);
        }
        __syncthreads();
    }

    float4 b0 = *reinterpret_cast<const float4*>(&bias[tx * 8]);
    float4 b1 = *reinterpret_cast<const float4*>(&bias[tx * 8 + 4]);
    float bv[8] = {b0.x, b0.y, b0.z, b0.w, b1.x, b1.y, b1.z, b1.w};
#pragma unroll
    for (int r = 0; r < 8; ++r) {
        int gr = row0 + ty * 8 + r;
        if (gr < n) {
            float o[8];
#pragma unroll
            for (int c = 0; c < 8; ++c) {
                o[c] = acc[r][c] + bv[c];
                if (RELU) o[c] = fmaxf(o[c], 0.0f);
            }
            *reinterpret_cast<float4*>(&C[gr * HO + tx * 8]) =
                make_float4(o[0], o[1], o[2], o[3]);
            *reinterpret_cast<float4*>(&C[gr * HO + tx * 8 + 4]) =
                make_float4(o[4], o[5], o[6], o[7]);
        }
    }
}

// Plain wrapper kernels referencing the device globals directly.
__global__ void kmm_one(const float* __restrict__ xin,
                        const float* __restrict__ W1l,
                        const float* __restrict__ W1r,
                        const float* __restrict__ b1, int n) {
    mm_body<64, 64, 128, true, true>(s_agA, xin, W1l, W1r, b1, s_t1, s_cnt, n);
}
__global__ void kmm_two(const float* __restrict__ Wlin1,
                        const float* __restrict__ blin1, int n) {
    mm_body<128, 0, 128, true, false>(s_t1, nullptr, Wlin1, nullptr, blin1, s_t2, s_cnt, n);
}
__global__ void kmm_three(const float* __restrict__ W2l,
                          const float* __restrict__ W2r,
                          const float* __restrict__ b2, int n) {
    mm_body<128, 128, 128, true, true>(s_agB, s_t2, W2l, W2r, b2, s_t3, s_cnt, n);
}
__global__ void kmm_four(const float* __restrict__ Wlin2,
                         const float* __restrict__ blin2,
                         float* __restrict__ outp, int n) {
    mm_body<128, 0, 64, false, false>(s_t3, nullptr, Wlin2, nullptr, blin2, outp, s_cnt, n);
}

// ---------------------------------------------------------------------------
// Launch. Inputs (metadata order): x, edge_index, W1l, b1, W1r, Wlin1, blin1,
//                                  W2l, b2, W2r, Wlin2, blin2
// ---------------------------------------------------------------------------
extern "C" void kernel_launch(void* const* d_in, const int* in_sizes, int n_in,
                              void* d_out, int out_size) {
    const float* xin   = (const float*)d_in[0];
    const int*   eidx  = (const int*)d_in[1];
    const float* W1l   = (const float*)d_in[2];
    const float* b1    = (const float*)d_in[3];
    const float* W1r   = (const float*)d_in[4];
    const float* Wlin1 = (const float*)d_in[5];
    const float* blin1 = (const float*)d_in[6];
    const float* W2l   = (const float*)d_in[7];
    const float* b2    = (const float*)d_in[8];
    const float* W2r   = (const float*)d_in[9];
    const float* Wlin2 = (const float*)d_in[10];
    const float* blin2 = (const float*)d_in[11];
    float*       outp  = (float*)d_out;

    const int n = in_sizes[0] / P_D;   // 100000
    const int E = in_sizes[1] / 2;     // 1600000

    kz_fill<<<1184, 256>>>(0);

    const int nblk = (n + 127) / 128;  // 128 rows per block

    // Layer 1 aggregation (+ degree): E*16 threads
    ksc_one<<<(E * 16 + 255) / 256, 256>>>(
        reinterpret_cast<const float4*>(xin), eidx, E);

    kmm_one<<<nblk, 256>>>(xin, W1l, W1r, b1, n);     // (128/8)*(128/8)=256
    kmm_two<<<nblk, 256>>>(Wlin1, blin1, n);

    // Layer 2 aggregation: E*32 threads
    {
        long long tot = (long long)E * 32;
        int grid = (int)((tot + 255) / 256);
        ksc_two<<<grid, 256>>>(eidx, E);
    }

    kmm_three<<<nblk, 256>>>(W2l, W2r, b2, n);
    kmm_four<<<nblk, 128>>>(Wlin2, blin2, outp, n);   // (64/8)*(128/8)=128
}

// round 9
// speedup vs baseline: 1.6523x; 1.0189x over previous
#include <cuda_runtime.h>
#include <cstdint>

// Problem constants (fixed by the dataset)
#define P_N 100000
#define P_D 64
#define P_H 128
#define P_O 64

// Scratch: __device__ globals, only ever touched from device code.
__device__ float s_agA[P_N * P_D];   // layer-1 neighbor sums   (25.6 MB)
__device__ float s_cnt[P_N];         // in-degree               (0.4 MB)
__device__ float s_t1 [P_N * P_H];   // h1                      (51.2 MB)
__device__ float s_t2 [P_N * P_H];   // h2                      (51.2 MB)
__device__ float s_agB[P_N * P_H];   // layer-2 neighbor sums   (51.2 MB)
__device__ float s_t3 [P_N * P_H];   // h3                      (51.2 MB)

__device__ __forceinline__ void red_add_v4(float* p, float4 v) {
    asm volatile("red.global.add.v4.f32 [%0], {%1, %2, %3, %4};"
                 :: "l"(p), "f"(v.x), "f"(v.y), "f"(v.z), "f"(v.w)
                 : "memory");
}

// Packed fp32x2 helpers (B300: fma.rn.f32x2 doubles fp32 FMA throughput)
__device__ __forceinline__ unsigned long long pack2(float lo, float hi) {
    unsigned long long r;
    asm("mov.b64 %0, {%1, %2};" : "=l"(r) : "f"(lo), "f"(hi));
    return r;
}
__device__ __forceinline__ void unpack2(float& lo, float& hi, unsigned long long v) {
    asm("mov.b64 {%0, %1}, %2;" : "=f"(lo), "=f"(hi) : "l"(v));
}
__device__ __forceinline__ unsigned long long fma2(unsigned long long a,
                                                   unsigned long long b,
                                                   unsigned long long c) {
    unsigned long long d;
    asm("fma.rn.f32x2 %0, %1, %2, %3;" : "=l"(d) : "l"(a), "l"(b), "l"(c));
    return d;
}

// ---------------------------------------------------------------------------
// Zero scratch accumulators (vector grid-stride).
// ---------------------------------------------------------------------------
__global__ void kz_fill(int dummy) {
    const float4 z = make_float4(0.f, 0.f, 0.f, 0.f);
    int idx = blockIdx.x * blockDim.x + threadIdx.x;
    int stride = gridDim.x * blockDim.x;
    for (int i = idx; i < P_N * P_D / 4; i += stride)
        reinterpret_cast<float4*>(s_agA)[i] = z;
    for (int i = idx; i < P_N * P_H / 4; i += stride)
        reinterpret_cast<float4*>(s_agB)[i] = z;
    for (int i = idx; i < P_N; i += stride)
        s_cnt[i] = 0.0f;
}

// ---------------------------------------------------------------------------
// Edge scatter, layer 1: s_agA[dst*64 + 4c..] += x[src*64 + 4c..]
// edge_index INT32: ei[0..E-1]=src, ei[E..2E-1]=dst. 16 chunks/edge, RED.128.
// ---------------------------------------------------------------------------
__global__ void ksc_one(const float4* __restrict__ x4,
                        const int* __restrict__ ei, int E) {
    int idx = blockIdx.x * blockDim.x + threadIdx.x;
    if (idx >= E * 16) return;
    int e = idx >> 4;
    int c = idx & 15;
    int src = ei[e];
    int dst = ei[E + e];
    float4 v = x4[src * 16 + c];
    red_add_v4(s_agA + dst * 64 + c * 4, v);
    if (c == 0) atomicAdd(&s_cnt[dst], 1.0f);
}

// ---------------------------------------------------------------------------
// Edge scatter, layer 2: s_agB[dst*128 + 4c..] += s_t2[src*128 + 4c..]
// ---------------------------------------------------------------------------
__global__ void ksc_two(const int* __restrict__ ei, int E) {
    long long idx = (long long)blockIdx.x * blockDim.x + threadIdx.x;
    if (idx >= (long long)E * 32) return;
    int e = (int)(idx >> 5);
    int c = (int)(idx & 31);
    int src = ei[e];
    int dst = ei[E + e];
    const float4* h2v = reinterpret_cast<const float4*>(s_t2);
    float4 v = h2v[src * 32 + c];
    red_add_v4(s_agB + dst * 128 + c * 4, v);
}

// ---------------------------------------------------------------------------
// Register-blocked GEMM with packed f32x2 math.
// C = act( scale(A1) @ W1 [+ A2 @ W2] + bias )
// Tile: MT=128 rows x HO cols per block; thread owns 8 rows x 8 cols
// (= 8 rows x 4 f32x2 col-pairs). W pairs come pre-packed from shared memory.
// ---------------------------------------------------------------------------
template<int K1, int K2, int HO, bool RELU, bool SC>
__device__ __forceinline__ void mm_body(const float* A1, const float* A2,
                                        const float* W1, const float* W2,
                                        const float* bias, float* C,
                                        const float* deg, int n) {
    constexpr int MT   = 128;
    constexpr int KT   = 32;
    constexpr int KTOT = K1 + K2;
    constexpr int AS   = MT + 4;      // 132: row stride, 16B-aligned
    constexpr int NTHR = (HO / 8) * (MT / 8);

    __shared__ __align__(16) float shA[KT * AS];
    __shared__ __align__(16) float shW[KT * HO];
    __shared__ float shS[MT];

    const int tid  = threadIdx.x;
    const int tx   = tid % (HO / 8);
    const int ty   = tid / (HO / 8);
    const int row0 = blockIdx.x * MT;

    if (SC) {
        for (int i = tid; i < MT; i += NTHR) {
            int gr = row0 + i;
            float d = (gr < n) ? deg[gr] : 1.0f;
            shS[i] = 1.0f / fmaxf(d, 1.0f);
        }
        __syncthreads();
    }

    unsigned long long acc2[8][4];
#pragma unroll
    for (int r = 0; r < 8; ++r)
#pragma unroll
        for (int c = 0; c < 4; ++c) acc2[r][c] = 0ull;

    for (int kt = 0; kt < KTOT; kt += KT) {
        // --- W tile (KT x HO), float4 coalesced ---
        const float* Wsrc = (kt < K1) ? (W1 + kt * HO) : (W2 + (kt - K1) * HO);
#pragma unroll
        for (int i = tid * 4; i < KT * HO; i += NTHR * 4)
            *reinterpret_cast<float4*>(&shW[i]) =
                *reinterpret_cast<const float4*>(&Wsrc[i]);

        // --- A tile transposed: float4 global loads, scalar transposed STS ---
        const float* Asrc;
        int kbase, KA;
        if (kt < K1) { Asrc = A1; kbase = kt;      KA = K1; }
        else         { Asrc = A2; kbase = kt - K1; KA = (K2 > 0) ? K2 : 1; }
#pragma unroll
        for (int i = tid; i < MT * (KT / 4); i += NTHR) {
            int r   = i / (KT / 4);
            int lk4 = i - r * (KT / 4);
            int gr  = row0 + r;
            float4 v = make_float4(0.f, 0.f, 0.f, 0.f);
            if (gr < n)
                v = *reinterpret_cast<const float4*>(&Asrc[gr * KA + kbase + lk4 * 4]);
            if (SC && kt < K1) {
                float s = shS[r];
                v.x *= s; v.y *= s; v.z *= s; v.w *= s;
            }
            shA[(lk4 * 4 + 0) * AS + r] = v.x;
            shA[(lk4 * 4 + 1) * AS + r] = v.y;
            shA[(lk4 * 4 + 2) * AS + r] = v.z;
            shA[(lk4 * 4 + 3) * AS + r] = v.w;
        }
        __syncthreads();

#pragma unroll 2
        for (int k = 0; k < KT; ++k) {
            // W col-pairs: contiguous floats = ready-packed f32x2 operands
            ulonglong2 wq0 = *reinterpret_cast<const ulonglong2*>(&shW[k * HO + tx * 8]);
            ulonglong2 wq1 = *reinterpret_cast<const ulonglong2*>(&shW[k * HO + tx * 8 + 4]);
            float4 a0 = *reinterpret_cast<const float4*>(&shA[k * AS + ty * 8]);
            float4 a1 = *reinterpret_cast<const float4*>(&shA[k * AS + ty * 8 + 4]);
            float av[8] = {a0.x, a0.y, a0.z, a0.w, a1.x, a1.y, a1.z, a1.w};
#pragma unroll
            for (int r = 0; r < 8; ++r) {
                unsigned long long ar = pack2(av[r], av[r]);
                acc2[r][0] = fma2(ar, wq0.x, acc2[r][0]);
                acc2[r][1] = fma2(ar, wq0.y, acc2[r][1]);
                acc2[r][2] = fma2(ar, wq1.x, acc2[r][2]);
                acc2[r][3] = fma2(ar, wq1.y, acc2[r][3]);
            }
        }
        __syncthreads();
    }

    float4 b0 = *reinterpret_cast<const float4*>(&bias[tx * 8]);
    float4 b1 = *reinterpret_cast<const float4*>(&bias[tx * 8 + 4]);
    float bv[8] = {b0.x, b0.y, b0.z, b0.w, b1.x, b1.y, b1.z, b1.w};
#pragma unroll
    for (int r = 0; r < 8; ++r) {
        int gr = row0 + ty * 8 + r;
        if (gr < n) {
            float o[8];
#pragma unroll
            for (int c = 0; c < 4; ++c)
                unpack2(o[2 * c], o[2 * c + 1], acc2[r][c]);
#pragma unroll
            for (int c = 0; c < 8; ++c) {
                o[c] += bv[c];
                if (RELU) o[c] = fmaxf(o[c], 0.0f);
            }
            *reinterpret_cast<float4*>(&C[gr * HO + tx * 8]) =
                make_float4(o[0], o[1], o[2], o[3]);
            *reinterpret_cast<float4*>(&C[gr * HO + tx * 8 + 4]) =
                make_float4(o[4], o[5], o[6], o[7]);
        }
    }
}

// Plain wrapper kernels referencing the device globals directly.
__global__ void kmm_one(const float* __restrict__ xin,
                        const float* __restrict__ W1l,
                        const float* __restrict__ W1r,
                        const float* __restrict__ b1, int n) {
    mm_body<64, 64, 128, true, true>(s_agA, xin, W1l, W1r, b1, s_t1, s_cnt, n);
}
__global__ void kmm_two(const float* __restrict__ Wlin1,
                        const float* __restrict__ blin1, int n) {
    mm_body<128, 0, 128, true, false>(s_t1, nullptr, Wlin1, nullptr, blin1, s_t2, s_cnt, n);
}
__global__ void kmm_three(const float* __restrict__ W2l,
                          const float* __restrict__ W2r,
                          const float* __restrict__ b2, int n) {
    mm_body<128, 128, 128, true, true>(s_agB, s_t2, W2l, W2r, b2, s_t3, s_cnt, n);
}
__global__ void kmm_four(const float* __restrict__ Wlin2,
                         const float* __restrict__ blin2,
                         float* __restrict__ outp, int n) {
    mm_body<128, 0, 64, false, false>(s_t3, nullptr, Wlin2, nullptr, blin2, outp, s_cnt, n);
}

// ---------------------------------------------------------------------------
// Launch. Inputs (metadata order): x, edge_index, W1l, b1, W1r, Wlin1, blin1,
//                                  W2l, b2, W2r, Wlin2, blin2
// ---------------------------------------------------------------------------
extern "C" void kernel_launch(void* const* d_in, const int* in_sizes, int n_in,
                              void* d_out, int out_size) {
    const float* xin   = (const float*)d_in[0];
    const int*   eidx  = (const int*)d_in[1];
    const float* W1l   = (const float*)d_in[2];
    const float* b1    = (const float*)d_in[3];
    const float* W1r   = (const float*)d_in[4];
    const float* Wlin1 = (const float*)d_in[5];
    const float* blin1 = (const float*)d_in[6];
    const float* W2l   = (const float*)d_in[7];
    const float* b2    = (const float*)d_in[8];
    const float* W2r   = (const float*)d_in[9];
    const float* Wlin2 = (const float*)d_in[10];
    const float* blin2 = (const float*)d_in[11];
    float*       outp  = (float*)d_out;

    const int n = in_sizes[0] / P_D;   // 100000
    const int E = in_sizes[1] / 2;     // 1600000

    kz_fill<<<1184, 256>>>(0);

    const int nblk = (n + 127) / 128;

    // Layer 1 aggregation (+ degree): E*16 threads
    ksc_one<<<(E * 16 + 255) / 256, 256>>>(
        reinterpret_cast<const float4*>(xin), eidx, E);

    kmm_one<<<nblk, 256>>>(xin, W1l, W1r, b1, n);
    kmm_two<<<nblk, 256>>>(Wlin1, blin1, n);

    // Layer 2 aggregation: E*32 threads
    {
        long long tot = (long long)E * 32;
        int grid = (int)((tot + 255) / 256);
        ksc_two<<<grid, 256>>>(eidx, E);
    }

    kmm_three<<<nblk, 256>>>(W2l, W2r, b2, n);
    kmm_four<<<nblk, 128>>>(Wlin2, blin2, outp, n);
}

// round 10
// speedup vs baseline: 1.7360x; 1.0506x over previous
#include <cuda_runtime.h>
#include <cstdint>

// Problem constants (fixed by the dataset)
#define P_N 100000
#define P_D 64
#define P_H 128
#define P_O 64

// Scratch: __device__ globals, only ever touched from device code.
__device__ float s_agA[P_N * P_D];   // layer-1 neighbor sums   (25.6 MB)
__device__ float s_cnt[P_N];         // in-degree               (0.4 MB)
__device__ float s_t1 [P_N * P_H];   // h1                      (51.2 MB)
__device__ float s_t2 [P_N * P_H];   // h2                      (51.2 MB)
__device__ float s_agB[P_N * P_H];   // layer-2 neighbor sums   (51.2 MB)
__device__ float s_t3 [P_N * P_H];   // h3                      (51.2 MB)

__device__ __forceinline__ void red_add_v4(float* p, float4 v) {
    asm volatile("red.global.add.v4.f32 [%0], {%1, %2, %3, %4};"
                 :: "l"(p), "f"(v.x), "f"(v.y), "f"(v.z), "f"(v.w)
                 : "memory");
}

// Packed fp32x2 helpers (B300: fma.rn.f32x2 doubles fp32 FMA throughput)
__device__ __forceinline__ unsigned long long pack2(float lo, float hi) {
    unsigned long long r;
    asm("mov.b64 %0, {%1, %2};" : "=l"(r) : "f"(lo), "f"(hi));
    return r;
}
__device__ __forceinline__ void unpack2(float& lo, float& hi, unsigned long long v) {
    asm("mov.b64 {%0, %1}, %2;" : "=f"(lo), "=f"(hi) : "l"(v));
}
__device__ __forceinline__ unsigned long long fma2(unsigned long long a,
                                                   unsigned long long b,
                                                   unsigned long long c) {
    unsigned long long d;
    asm("fma.rn.f32x2 %0, %1, %2, %3;" : "=l"(d) : "l"(a), "l"(b), "l"(c));
    return d;
}

// ---------------------------------------------------------------------------
// Zero scratch accumulators (vector grid-stride).
// ---------------------------------------------------------------------------
__global__ void kz_fill(int dummy) {
    const float4 z = make_float4(0.f, 0.f, 0.f, 0.f);
    int idx = blockIdx.x * blockDim.x + threadIdx.x;
    int stride = gridDim.x * blockDim.x;
    for (int i = idx; i < P_N * P_D / 4; i += stride)
        reinterpret_cast<float4*>(s_agA)[i] = z;
    for (int i = idx; i < P_N * P_H / 4; i += stride)
        reinterpret_cast<float4*>(s_agB)[i] = z;
    for (int i = idx; i < P_N; i += stride)
        s_cnt[i] = 0.0f;
}

// ---------------------------------------------------------------------------
// Edge scatter, layer 1: s_agA[dst*64 + 4c..] += x[src*64 + 4c..]
// edge_index INT32: ei[0..E-1]=src, ei[E..2E-1]=dst. 16 chunks/edge, RED.128.
// ---------------------------------------------------------------------------
__global__ void ksc_one(const float4* __restrict__ x4,
                        const int* __restrict__ ei, int E) {
    int idx = blockIdx.x * blockDim.x + threadIdx.x;
    if (idx >= E * 16) return;
    int e = idx >> 4;
    int c = idx & 15;
    int src = ei[e];
    int dst = ei[E + e];
    float4 v = x4[src * 16 + c];
    red_add_v4(s_agA + dst * 64 + c * 4, v);
    if (c == 0) atomicAdd(&s_cnt[dst], 1.0f);
}

// ---------------------------------------------------------------------------
// Edge scatter, layer 2: s_agB[dst*128 + 4c..] += s_t2[src*128 + 4c..]
// ---------------------------------------------------------------------------
__global__ void ksc_two(const int* __restrict__ ei, int E) {
    long long idx = (long long)blockIdx.x * blockDim.x + threadIdx.x;
    if (idx >= (long long)E * 32) return;
    int e = (int)(idx >> 5);
    int c = (int)(idx & 31);
    int src = ei[e];
    int dst = ei[E + e];
    const float4* h2v = reinterpret_cast<const float4*>(s_t2);
    float4 v = h2v[src * 32 + c];
    red_add_v4(s_agB + dst * 128 + c * 4, v);
}

// ---------------------------------------------------------------------------
// Register-blocked GEMM, packed f32x2 math, software-pipelined inner loop.
// C = act( scale(A1) @ W1 [+ A2 @ W2] + bias )
// Tile: MT=128 rows x HO cols; thread owns 8 rows x 8 cols (4 f32x2 pairs).
// k-loop prefetches k+1's LDS operands before k's 32 fma2s -> LDS latency
// hidden by in-thread ILP, not occupancy.
// ---------------------------------------------------------------------------
template<int K1, int K2, int HO, bool RELU, bool SC>
__device__ __forceinline__ void mm_body(const float* A1, const float* A2,
                                        const float* W1, const float* W2,
                                        const float* bias, float* C,
                                        const float* deg, int n) {
    constexpr int MT   = 128;
    constexpr int KT   = 32;
    constexpr int KTOT = K1 + K2;
    constexpr int AS   = MT + 4;      // 132: row stride, 16B-aligned
    constexpr int NTHR = (HO / 8) * (MT / 8);

    __shared__ __align__(16) float shA[KT * AS];
    __shared__ __align__(16) float shW[KT * HO];
    __shared__ float shS[MT];

    const int tid  = threadIdx.x;
    const int tx   = tid % (HO / 8);
    const int ty   = tid / (HO / 8);
    const int row0 = blockIdx.x * MT;

    if (SC) {
        for (int i = tid; i < MT; i += NTHR) {
            int gr = row0 + i;
            float d = (gr < n) ? deg[gr] : 1.0f;
            shS[i] = 1.0f / fmaxf(d, 1.0f);
        }
        __syncthreads();
    }

    unsigned long long acc2[8][4];
#pragma unroll
    for (int r = 0; r < 8; ++r)
#pragma unroll
        for (int c = 0; c < 4; ++c) acc2[r][c] = 0ull;

    const float* shWt = &shW[tx * 8];
    const float* shAt = &shA[ty * 8];

    for (int kt = 0; kt < KTOT; kt += KT) {
        // --- W tile (KT x HO), float4 coalesced ---
        const float* Wsrc = (kt < K1) ? (W1 + kt * HO) : (W2 + (kt - K1) * HO);
#pragma unroll
        for (int i = tid * 4; i < KT * HO; i += NTHR * 4)
            *reinterpret_cast<float4*>(&shW[i]) =
                *reinterpret_cast<const float4*>(&Wsrc[i]);

        // --- A tile transposed: float4 global loads, scalar transposed STS ---
        const float* Asrc;
        int kbase, KA;
        if (kt < K1) { Asrc = A1; kbase = kt;      KA = K1; }
        else         { Asrc = A2; kbase = kt - K1; KA = (K2 > 0) ? K2 : 1; }
#pragma unroll
        for (int i = tid; i < MT * (KT / 4); i += NTHR) {
            int r   = i / (KT / 4);
            int lk4 = i - r * (KT / 4);
            int gr  = row0 + r;
            float4 v = make_float4(0.f, 0.f, 0.f, 0.f);
            if (gr < n)
                v = *reinterpret_cast<const float4*>(&Asrc[gr * KA + kbase + lk4 * 4]);
            if (SC && kt < K1) {
                float s = shS[r];
                v.x *= s; v.y *= s; v.z *= s; v.w *= s;
            }
            shA[(lk4 * 4 + 0) * AS + r] = v.x;
            shA[(lk4 * 4 + 1) * AS + r] = v.y;
            shA[(lk4 * 4 + 2) * AS + r] = v.z;
            shA[(lk4 * 4 + 3) * AS + r] = v.w;
        }
        __syncthreads();

        // --- software-pipelined inner loop ---
        ulonglong2 wq0 = *reinterpret_cast<const ulonglong2*>(&shWt[0]);
        ulonglong2 wq1 = *reinterpret_cast<const ulonglong2*>(&shWt[4]);
        float4 a0 = *reinterpret_cast<const float4*>(&shAt[0]);
        float4 a1 = *reinterpret_cast<const float4*>(&shAt[4]);

#pragma unroll
        for (int k = 0; k < KT; ++k) {
            const int kn = (k + 1 < KT) ? (k + 1) : k;   // clamp: last prefetch unused
            ulonglong2 nw0 = *reinterpret_cast<const ulonglong2*>(&shWt[kn * HO]);
            ulonglong2 nw1 = *reinterpret_cast<const ulonglong2*>(&shWt[kn * HO + 4]);
            float4 na0 = *reinterpret_cast<const float4*>(&shAt[kn * AS]);
            float4 na1 = *reinterpret_cast<const float4*>(&shAt[kn * AS + 4]);

            float av[8] = {a0.x, a0.y, a0.z, a0.w, a1.x, a1.y, a1.z, a1.w};
            unsigned long long ap[8];
#pragma unroll
            for (int r = 0; r < 8; ++r) ap[r] = pack2(av[r], av[r]);
#pragma unroll
            for (int r = 0; r < 8; ++r) {
                acc2[r][0] = fma2(ap[r], wq0.x, acc2[r][0]);
                acc2[r][1] = fma2(ap[r], wq0.y, acc2[r][1]);
                acc2[r][2] = fma2(ap[r], wq1.x, acc2[r][2]);
                acc2[r][3] = fma2(ap[r], wq1.y, acc2[r][3]);
            }
            wq0 = nw0; wq1 = nw1; a0 = na0; a1 = na1;
        }
        __syncthreads();
    }

    float4 b0 = *reinterpret_cast<const float4*>(&bias[tx * 8]);
    float4 b1 = *reinterpret_cast<const float4*>(&bias[tx * 8 + 4]);
    float bv[8] = {b0.x, b0.y, b0.z, b0.w, b1.x, b1.y, b1.z, b1.w};
#pragma unroll
    for (int r = 0; r < 8; ++r) {
        int gr = row0 + ty * 8 + r;
        if (gr < n) {
            float o[8];
#pragma unroll
            for (int c = 0; c < 4; ++c)
                unpack2(o[2 * c], o[2 * c + 1], acc2[r][c]);
#pragma unroll
            for (int c = 0; c < 8; ++c) {
                o[c] += bv[c];
                if (RELU) o[c] = fmaxf(o[c], 0.0f);
            }
            *reinterpret_cast<float4*>(&C[gr * HO + tx * 8]) =
                make_float4(o[0], o[1], o[2], o[3]);
            *reinterpret_cast<float4*>(&C[gr * HO + tx * 8 + 4]) =
                make_float4(o[4], o[5], o[6], o[7]);
        }
    }
}

// Plain wrapper kernels referencing the device globals directly.
__global__ void __launch_bounds__(256, 2)
kmm_one(const float* __restrict__ xin,
        const float* __restrict__ W1l,
        const float* __restrict__ W1r,
        const float* __restrict__ b1, int n) {
    mm_body<64, 64, 128, true, true>(s_agA, xin, W1l, W1r, b1, s_t1, s_cnt, n);
}
__global__ void __launch_bounds__(256, 2)
kmm_two(const float* __restrict__ Wlin1,
        const float* __restrict__ blin1, int n) {
    mm_body<128, 0, 128, true, false>(s_t1, nullptr, Wlin1, nullptr, blin1, s_t2, s_cnt, n);
}
__global__ void __launch_bounds__(256, 2)
kmm_three(const float* __restrict__ W2l,
          const float* __restrict__ W2r,
          const float* __restrict__ b2, int n) {
    mm_body<128, 128, 128, true, true>(s_agB, s_t2, W2l, W2r, b2, s_t3, s_cnt, n);
}
__global__ void __launch_bounds__(128, 2)
kmm_four(const float* __restrict__ Wlin2,
         const float* __restrict__ blin2,
         float* __restrict__ outp, int n) {
    mm_body<128, 0, 64, false, false>(s_t3, nullptr, Wlin2, nullptr, blin2, outp, s_cnt, n);
}

// ---------------------------------------------------------------------------
// Launch. Inputs (metadata order): x, edge_index, W1l, b1, W1r, Wlin1, blin1,
//                                  W2l, b2, W2r, Wlin2, blin2
// ---------------------------------------------------------------------------
extern "C" void kernel_launch(void* const* d_in, const int* in_sizes, int n_in,
                              void* d_out, int out_size) {
    const float* xin   = (const float*)d_in[0];
    const int*   eidx  = (const int*)d_in[1];
    const float* W1l   = (const float*)d_in[2];
    const float* b1    = (const float*)d_in[3];
    const float* W1r   = (const float*)d_in[4];
    const float* Wlin1 = (const float*)d_in[5];
    const float* blin1 = (const float*)d_in[6];
    const float* W2l   = (const float*)d_in[7];
    const float* b2    = (const float*)d_in[8];
    const float* W2r   = (const float*)d_in[9];
    const float* Wlin2 = (const float*)d_in[10];
    const float* blin2 = (const float*)d_in[11];
    float*       outp  = (float*)d_out;

    const int n = in_sizes[0] / P_D;   // 100000
    const int E = in_sizes[1] / 2;     // 1600000

    kz_fill<<<1184, 256>>>(0);

    const int nblk = (n + 127) / 128;

    // Layer 1 aggregation (+ degree): E*16 threads
    ksc_one<<<(E * 16 + 255) / 256, 256>>>(
        reinterpret_cast<const float4*>(xin), eidx, E);

    kmm_one<<<nblk, 256>>>(xin, W1l, W1r, b1, n);
    kmm_two<<<nblk, 256>>>(Wlin1, blin1, n);

    // Layer 2 aggregation: E*32 threads
    {
        long long tot = (long long)E * 32;
        int grid = (int)((tot + 255) / 256);
        ksc_two<<<grid, 256>>>(eidx, E);
    }

    kmm_three<<<nblk, 256>>>(W2l, W2r, b2, n);
    kmm_four<<<nblk, 128>>>(Wlin2, blin2, outp, n);
}

// round 11
// speedup vs baseline: 1.7528x; 1.0097x over previous
#include <cuda_runtime.h>
#include <cstdint>

// Problem constants (fixed by the dataset)
#define P_N 100000
#define P_E 1600000
#define P_D 64
#define P_H 128
#define P_O 64

// Scratch: __device__ globals, only ever touched from device code.
__device__ float s_agA[P_N * P_D];     // layer-1 neighbor means  (25.6 MB)
__device__ float s_t1 [P_N * P_H];     // h1                      (51.2 MB)
__device__ float s_t2 [P_N * P_H];     // h2                      (51.2 MB)
__device__ float s_agB[P_N * P_H];     // layer-2 neighbor means  (51.2 MB)
__device__ float s_t3 [P_N * P_H];     // h3                      (51.2 MB)
// CSR scratch
__device__ int   g_ecnt  [P_N + 1];    // per-dst edge count
__device__ int   g_rowptr[P_N + 1];    // exclusive prefix
__device__ int   g_cursor[P_N + 1];    // fill cursors
__device__ int   g_srcs  [P_E];        // src ids binned by dst   (6.4 MB)

// Packed fp32x2 helpers (B300: fma.rn.f32x2 doubles fp32 FMA throughput)
__device__ __forceinline__ unsigned long long pack2(float lo, float hi) {
    unsigned long long r;
    asm("mov.b64 %0, {%1, %2};" : "=l"(r) : "f"(lo), "f"(hi));
    return r;
}
__device__ __forceinline__ void unpack2(float& lo, float& hi, unsigned long long v) {
    asm("mov.b64 {%0, %1}, %2;" : "=f"(lo), "=f"(hi) : "l"(v));
}
__device__ __forceinline__ unsigned long long fma2(unsigned long long a,
                                                   unsigned long long b,
                                                   unsigned long long c) {
    unsigned long long d;
    asm("fma.rn.f32x2 %0, %1, %2, %3;" : "=l"(d) : "l"(a), "l"(b), "l"(c));
    return d;
}

// ---------------------------------------------------------------------------
// CSR build step 1: zero counts.
// ---------------------------------------------------------------------------
__global__ void kcsr_zero() {
    int i = blockIdx.x * blockDim.x + threadIdx.x;
    if (i <= P_N) g_ecnt[i] = 0;
}

// CSR build step 2: histogram destinations.
__global__ void kcsr_hist(const int* __restrict__ ei, int E) {
    int e = blockIdx.x * blockDim.x + threadIdx.x;
    if (e >= E) return;
    atomicAdd(&g_ecnt[ei[E + e]], 1);
}

// CSR build step 3: exclusive scan (single block, 1024 threads).
__global__ void kcsr_scan() {
    __shared__ int part[1024];
    const int tid   = threadIdx.x;
    const int chunk = (P_N + 1023) / 1024;           // 98
    int lo = tid * chunk;
    int hi = lo + chunk; if (hi > P_N) hi = P_N;
    if (lo > P_N) lo = P_N;
    int s = 0;
    for (int i = lo; i < hi; ++i) s += g_ecnt[i];
    part[tid] = s;
    __syncthreads();
    for (int off = 1; off < 1024; off <<= 1) {
        int v = 0;
        if (tid >= off) v = part[tid - off];
        __syncthreads();
        if (tid >= off) part[tid] += v;
        __syncthreads();
    }
    int run = part[tid] - s;                         // exclusive prefix
    for (int i = lo; i < hi; ++i) {
        g_rowptr[i] = run;
        g_cursor[i] = run;
        run += g_ecnt[i];
    }
    if (hi == P_N) g_rowptr[P_N] = run;              // all such threads write E
}

// CSR build step 4: bin src ids by dst.
__global__ void kcsr_fill(const int* __restrict__ ei, int E) {
    int e = blockIdx.x * blockDim.x + threadIdx.x;
    if (e >= E) return;
    int dst = ei[E + e];
    int pos = atomicAdd(&g_cursor[dst], 1);
    g_srcs[pos] = ei[e];
}

// ---------------------------------------------------------------------------
// Gather layer 1: s_agA[i] = mean over CSR row i of x[src]  (D=64).
// One warp per node; lane owns 2 floats; 256B coalesced read per edge.
// ---------------------------------------------------------------------------
__global__ void kg_one(const float2* __restrict__ x2) {
    int w    = (blockIdx.x * blockDim.x + threadIdx.x) >> 5;
    int lane = threadIdx.x & 31;
    if (w >= P_N) return;
    int lo = g_rowptr[w], hi = g_rowptr[w + 1];
    float ax0 = 0.f, ay0 = 0.f, ax1 = 0.f, ay1 = 0.f;
    int e = lo;
    for (; e + 1 < hi; e += 2) {
        int s0 = g_srcs[e], s1 = g_srcs[e + 1];
        float2 v0 = x2[s0 * 32 + lane];
        float2 v1 = x2[s1 * 32 + lane];
        ax0 += v0.x; ay0 += v0.y;
        ax1 += v1.x; ay1 += v1.y;
    }
    if (e < hi) {
        float2 v = x2[g_srcs[e] * 32 + lane];
        ax0 += v.x; ay0 += v.y;
    }
    int deg = hi - lo;
    float inv = (deg > 0) ? (1.0f / (float)deg) : 1.0f;
    float2 o;
    o.x = (ax0 + ax1) * inv;
    o.y = (ay0 + ay1) * inv;
    reinterpret_cast<float2*>(s_agA)[w * 32 + lane] = o;
}

// ---------------------------------------------------------------------------
// Gather layer 2: s_agB[i] = mean over CSR row i of s_t2[src]  (H=128).
// Lane owns 4 floats; 512B coalesced read per edge.
// ---------------------------------------------------------------------------
__global__ void kg_two(int dummy) {
    int w    = (blockIdx.x * blockDim.x + threadIdx.x) >> 5;
    int lane = threadIdx.x & 31;
    if (w >= P_N) return;
    int lo = g_rowptr[w], hi = g_rowptr[w + 1];
    const float4* h4 = reinterpret_cast<const float4*>(s_t2);
    float a0[4] = {0.f, 0.f, 0.f, 0.f};
    float a1[4] = {0.f, 0.f, 0.f, 0.f};
    int e = lo;
    for (; e + 1 < hi; e += 2) {
        int s0 = g_srcs[e], s1 = g_srcs[e + 1];
        float4 v0 = h4[s0 * 32 + lane];
        float4 v1 = h4[s1 * 32 + lane];
        a0[0] += v0.x; a0[1] += v0.y; a0[2] += v0.z; a0[3] += v0.w;
        a1[0] += v1.x; a1[1] += v1.y; a1[2] += v1.z; a1[3] += v1.w;
    }
    if (e < hi) {
        float4 v = h4[g_srcs[e] * 32 + lane];
        a0[0] += v.x; a0[1] += v.y; a0[2] += v.z; a0[3] += v.w;
    }
    int deg = hi - lo;
    float inv = (deg > 0) ? (1.0f / (float)deg) : 1.0f;
    float4 o;
    o.x = (a0[0] + a1[0]) * inv;
    o.y = (a0[1] + a1[1]) * inv;
    o.z = (a0[2] + a1[2]) * inv;
    o.w = (a0[3] + a1[3]) * inv;
    reinterpret_cast<float4*>(s_agB)[w * 32 + lane] = o;
}

// ---------------------------------------------------------------------------
// Register-blocked GEMM, packed f32x2 math, software-pipelined inner loop.
// C = act( A1 @ W1 [+ A2 @ W2] + bias )   (means pre-folded in gathers)
// ---------------------------------------------------------------------------
template<int K1, int K2, int HO, bool RELU>
__device__ __forceinline__ void mm_body(const float* A1, const float* A2,
                                        const float* W1, const float* W2,
                                        const float* bias, float* C, int n) {
    constexpr int MT   = 128;
    constexpr int KT   = 32;
    constexpr int KTOT = K1 + K2;
    constexpr int AS   = MT + 4;
    constexpr int NTHR = (HO / 8) * (MT / 8);

    __shared__ __align__(16) float shA[KT * AS];
    __shared__ __align__(16) float shW[KT * HO];

    const int tid  = threadIdx.x;
    const int tx   = tid % (HO / 8);
    const int ty   = tid / (HO / 8);
    const int row0 = blockIdx.x * MT;

    unsigned long long acc2[8][4];
#pragma unroll
    for (int r = 0; r < 8; ++r)
#pragma unroll
        for (int c = 0; c < 4; ++c) acc2[r][c] = 0ull;

    const float* shWt = &shW[tx * 8];
    const float* shAt = &shA[ty * 8];

    for (int kt = 0; kt < KTOT; kt += KT) {
        const float* Wsrc = (kt < K1) ? (W1 + kt * HO) : (W2 + (kt - K1) * HO);
#pragma unroll
        for (int i = tid * 4; i < KT * HO; i += NTHR * 4)
            *reinterpret_cast<float4*>(&shW[i]) =
                *reinterpret_cast<const float4*>(&Wsrc[i]);

        const float* Asrc;
        int kbase, KA;
        if (kt < K1) { Asrc = A1; kbase = kt;      KA = K1; }
        else         { Asrc = A2; kbase = kt - K1; KA = (K2 > 0) ? K2 : 1; }
#pragma unroll
        for (int i = tid; i < MT * (KT / 4); i += NTHR) {
            int r   = i / (KT / 4);
            int lk4 = i - r * (KT / 4);
            int gr  = row0 + r;
            float4 v = make_float4(0.f, 0.f, 0.f, 0.f);
            if (gr < n)
                v = *reinterpret_cast<const float4*>(&Asrc[gr * KA + kbase + lk4 * 4]);
            shA[(lk4 * 4 + 0) * AS + r] = v.x;
            shA[(lk4 * 4 + 1) * AS + r] = v.y;
            shA[(lk4 * 4 + 2) * AS + r] = v.z;
            shA[(lk4 * 4 + 3) * AS + r] = v.w;
        }
        __syncthreads();

        ulonglong2 wq0 = *reinterpret_cast<const ulonglong2*>(&shWt[0]);
        ulonglong2 wq1 = *reinterpret_cast<const ulonglong2*>(&shWt[4]);
        float4 a0 = *reinterpret_cast<const float4*>(&shAt[0]);
        float4 a1 = *reinterpret_cast<const float4*>(&shAt[4]);

#pragma unroll
        for (int k = 0; k < KT; ++k) {
            const int kn = (k + 1 < KT) ? (k + 1) : k;
            ulonglong2 nw0 = *reinterpret_cast<const ulonglong2*>(&shWt[kn * HO]);
            ulonglong2 nw1 = *reinterpret_cast<const ulonglong2*>(&shWt[kn * HO + 4]);
            float4 na0 = *reinterpret_cast<const float4*>(&shAt[kn * AS]);
            float4 na1 = *reinterpret_cast<const float4*>(&shAt[kn * AS + 4]);

            float av[8] = {a0.x, a0.y, a0.z, a0.w, a1.x, a1.y, a1.z, a1.w};
            unsigned long long ap[8];
#pragma unroll
            for (int r = 0; r < 8; ++r) ap[r] = pack2(av[r], av[r]);
#pragma unroll
            for (int r = 0; r < 8; ++r) {
                acc2[r][0] = fma2(ap[r], wq0.x, acc2[r][0]);
                acc2[r][1] = fma2(ap[r], wq0.y, acc2[r][1]);
                acc2[r][2] = fma2(ap[r], wq1.x, acc2[r][2]);
                acc2[r][3] = fma2(ap[r], wq1.y, acc2[r][3]);
            }
            wq0 = nw0; wq1 = nw1; a0 = na0; a1 = na1;
        }
        __syncthreads();
    }

    float4 b0 = *reinterpret_cast<const float4*>(&bias[tx * 8]);
    float4 b1 = *reinterpret_cast<const float4*>(&bias[tx * 8 + 4]);
    float bv[8] = {b0.x, b0.y, b0.z, b0.w, b1.x, b1.y, b1.z, b1.w};
#pragma unroll
    for (int r = 0; r < 8; ++r) {
        int gr = row0 + ty * 8 + r;
        if (gr < n) {
            float o[8];
#pragma unroll
            for (int c = 0; c < 4; ++c)
                unpack2(o[2 * c], o[2 * c + 1], acc2[r][c]);
#pragma unroll
            for (int c = 0; c < 8; ++c) {
                o[c] += bv[c];
                if (RELU) o[c] = fmaxf(o[c], 0.0f);
            }
            *reinterpret_cast<float4*>(&C[gr * HO + tx * 8]) =
                make_float4(o[0], o[1], o[2], o[3]);
            *reinterpret_cast<float4*>(&C[gr * HO + tx * 8 + 4]) =
                make_float4(o[4], o[5], o[6], o[7]);
        }
    }
}

__global__ void __launch_bounds__(256, 2)
kmm_one(const float* __restrict__ xin,
        const float* __restrict__ W1l,
        const float* __restrict__ W1r,
        const float* __restrict__ b1, int n) {
    mm_body<64, 64, 128, true>(s_agA, xin, W1l, W1r, b1, s_t1, n);
}
__global__ void __launch_bounds__(256, 2)
kmm_two(const float* __restrict__ Wlin1,
        const float* __restrict__ blin1, int n) {
    mm_body<128, 0, 128, true>(s_t1, nullptr, Wlin1, nullptr, blin1, s_t2, n);
}
__global__ void __launch_bounds__(256, 2)
kmm_three(const float* __restrict__ W2l,
          const float* __restrict__ W2r,
          const float* __restrict__ b2, int n) {
    mm_body<128, 128, 128, true>(s_agB, s_t2, W2l, W2r, b2, s_t3, n);
}
__global__ void __launch_bounds__(128, 2)
kmm_four(const float* __restrict__ Wlin2,
         const float* __restrict__ blin2,
         float* __restrict__ outp, int n) {
    mm_body<128, 0, 64, false>(s_t3, nullptr, Wlin2, nullptr, blin2, outp, n);
}

// ---------------------------------------------------------------------------
// Launch. Inputs (metadata order): x, edge_index, W1l, b1, W1r, Wlin1, blin1,
//                                  W2l, b2, W2r, Wlin2, blin2
// ---------------------------------------------------------------------------
extern "C" void kernel_launch(void* const* d_in, const int* in_sizes, int n_in,
                              void* d_out, int out_size) {
    const float* xin   = (const float*)d_in[0];
    const int*   eidx  = (const int*)d_in[1];
    const float* W1l   = (const float*)d_in[2];
    const float* b1    = (const float*)d_in[3];
    const float* W1r   = (const float*)d_in[4];
    const float* Wlin1 = (const float*)d_in[5];
    const float* blin1 = (const float*)d_in[6];
    const float* W2l   = (const float*)d_in[7];
    const float* b2    = (const float*)d_in[8];
    const float* W2r   = (const float*)d_in[9];
    const float* Wlin2 = (const float*)d_in[10];
    const float* blin2 = (const float*)d_in[11];
    float*       outp  = (float*)d_out;

    const int n = in_sizes[0] / P_D;   // 100000
    const int E = in_sizes[1] / 2;     // 1600000

    // --- CSR build (once; shared by both layers) ---
    kcsr_zero<<<(P_N + 256) / 256, 256>>>();
    kcsr_hist<<<(E + 255) / 256, 256>>>(eidx, E);
    kcsr_scan<<<1, 1024>>>();
    kcsr_fill<<<(E + 255) / 256, 256>>>(eidx, E);

    const int nblk  = (n + 127) / 128;
    const int nblkG = (n + 7) / 8;     // warp per node, 8 warps/block

    // Layer 1: gather + fused GEMM
    kg_one<<<nblkG, 256>>>(reinterpret_cast<const float2*>(xin));
    kmm_one<<<nblk, 256>>>(xin, W1l, W1r, b1, n);
    kmm_two<<<nblk, 256>>>(Wlin1, blin1, n);

    // Layer 2: gather + fused GEMM
    kg_two<<<nblkG, 256>>>(0);
    kmm_three<<<nblk, 256>>>(W2l, W2r, b2, n);
    kmm_four<<<nblk, 128>>>(Wlin2, blin2, outp, n);
}

// round 12
// speedup vs baseline: 1.7666x; 1.0079x over previous
#include <cuda_runtime.h>
#include <cstdint>

// Problem constants (fixed by the dataset)
#define P_N 100000
#define P_E 1600000
#define P_D 64
#define P_H 128
#define P_O 64

// Scratch: __device__ globals, only ever touched from device code.
__device__ float s_agA[P_N * P_D];     // layer-1 neighbor means  (25.6 MB)
__device__ float s_t1 [P_N * P_H];     // h1                      (51.2 MB)
__device__ float s_t2 [P_N * P_H];     // h2                      (51.2 MB)
__device__ float s_agB[P_N * P_H];     // layer-2 neighbor means  (51.2 MB)
__device__ float s_t3 [P_N * P_H];     // h3                      (51.2 MB)
// CSR scratch
__device__ int   g_ecnt  [P_N + 1];
__device__ int   g_rowptr[P_N + 1];
__device__ int   g_cursor[P_N + 1];
__device__ int   g_srcs  [P_E];

// Packed fp32x2 helpers (B300: fma.rn.f32x2 doubles fp32 FMA throughput)
__device__ __forceinline__ unsigned long long pack2(float lo, float hi) {
    unsigned long long r;
    asm("mov.b64 %0, {%1, %2};" : "=l"(r) : "f"(lo), "f"(hi));
    return r;
}
__device__ __forceinline__ void unpack2(float& lo, float& hi, unsigned long long v) {
    asm("mov.b64 {%0, %1}, %2;" : "=f"(lo), "=f"(hi) : "l"(v));
}
__device__ __forceinline__ unsigned long long fma2(unsigned long long a,
                                                   unsigned long long b,
                                                   unsigned long long c) {
    unsigned long long d;
    asm("fma.rn.f32x2 %0, %1, %2, %3;" : "=l"(d) : "l"(a), "l"(b), "l"(c));
    return d;
}

// ---------------------------------------------------------------------------
// CSR build
// ---------------------------------------------------------------------------
__global__ void kcsr_zero() {
    int i = blockIdx.x * blockDim.x + threadIdx.x;
    if (i <= P_N) g_ecnt[i] = 0;
}
__global__ void kcsr_hist(const int* __restrict__ ei, int E) {
    int e = blockIdx.x * blockDim.x + threadIdx.x;
    if (e >= E) return;
    atomicAdd(&g_ecnt[ei[E + e]], 1);
}
__global__ void kcsr_scan() {
    __shared__ int part[1024];
    const int tid   = threadIdx.x;
    const int chunk = (P_N + 1023) / 1024;
    int lo = tid * chunk;
    int hi = lo + chunk; if (hi > P_N) hi = P_N;
    if (lo > P_N) lo = P_N;
    int s = 0;
    for (int i = lo; i < hi; ++i) s += g_ecnt[i];
    part[tid] = s;
    __syncthreads();
    for (int off = 1; off < 1024; off <<= 1) {
        int v = 0;
        if (tid >= off) v = part[tid - off];
        __syncthreads();
        if (tid >= off) part[tid] += v;
        __syncthreads();
    }
    int run = part[tid] - s;
    for (int i = lo; i < hi; ++i) {
        g_rowptr[i] = run;
        g_cursor[i] = run;
        run += g_ecnt[i];
    }
    if (hi == P_N) g_rowptr[P_N] = run;
}
__global__ void kcsr_fill(const int* __restrict__ ei, int E) {
    int e = blockIdx.x * blockDim.x + threadIdx.x;
    if (e >= E) return;
    int dst = ei[E + e];
    int pos = atomicAdd(&g_cursor[dst], 1);
    g_srcs[pos] = ei[e];
}

// ---------------------------------------------------------------------------
// Gather layer 1: s_agA[i] = mean over CSR row i of x[src]  (D=64).
// ---------------------------------------------------------------------------
__global__ void kg_one(const float2* __restrict__ x2) {
    int w    = (blockIdx.x * blockDim.x + threadIdx.x) >> 5;
    int lane = threadIdx.x & 31;
    if (w >= P_N) return;
    int lo = g_rowptr[w], hi = g_rowptr[w + 1];
    float ax0 = 0.f, ay0 = 0.f, ax1 = 0.f, ay1 = 0.f;
    int e = lo;
    for (; e + 1 < hi; e += 2) {
        int s0 = g_srcs[e], s1 = g_srcs[e + 1];
        float2 v0 = x2[s0 * 32 + lane];
        float2 v1 = x2[s1 * 32 + lane];
        ax0 += v0.x; ay0 += v0.y;
        ax1 += v1.x; ay1 += v1.y;
    }
    if (e < hi) {
        float2 v = x2[g_srcs[e] * 32 + lane];
        ax0 += v.x; ay0 += v.y;
    }
    int deg = hi - lo;
    float inv = (deg > 0) ? (1.0f / (float)deg) : 1.0f;
    float2 o;
    o.x = (ax0 + ax1) * inv;
    o.y = (ay0 + ay1) * inv;
    reinterpret_cast<float2*>(s_agA)[w * 32 + lane] = o;
}

// ---------------------------------------------------------------------------
// Gather layer 2: s_agB[i] = mean over CSR row i of s_t2[src]  (H=128).
// ---------------------------------------------------------------------------
__global__ void kg_two(int dummy) {
    int w    = (blockIdx.x * blockDim.x + threadIdx.x) >> 5;
    int lane = threadIdx.x & 31;
    if (w >= P_N) return;
    int lo = g_rowptr[w], hi = g_rowptr[w + 1];
    const float4* h4 = reinterpret_cast<const float4*>(s_t2);
    float a0[4] = {0.f, 0.f, 0.f, 0.f};
    float a1[4] = {0.f, 0.f, 0.f, 0.f};
    int e = lo;
    for (; e + 1 < hi; e += 2) {
        int s0 = g_srcs[e], s1 = g_srcs[e + 1];
        float4 v0 = h4[s0 * 32 + lane];
        float4 v1 = h4[s1 * 32 + lane];
        a0[0] += v0.x; a0[1] += v0.y; a0[2] += v0.z; a0[3] += v0.w;
        a1[0] += v1.x; a1[1] += v1.y; a1[2] += v1.z; a1[3] += v1.w;
    }
    if (e < hi) {
        float4 v = h4[g_srcs[e] * 32 + lane];
        a0[0] += v.x; a0[1] += v.y; a0[2] += v.z; a0[3] += v.w;
    }
    int deg = hi - lo;
    float inv = (deg > 0) ? (1.0f / (float)deg) : 1.0f;
    float4 o;
    o.x = (a0[0] + a1[0]) * inv;
    o.y = (a0[1] + a1[1]) * inv;
    o.z = (a0[2] + a1[2]) * inv;
    o.w = (a0[3] + a1[3]) * inv;
    reinterpret_cast<float4*>(s_agB)[w * 32 + lane] = o;
}

// ---------------------------------------------------------------------------
// Register-blocked GEMM, packed f32x2 math, DOUBLE-BUFFERED k-stages.
// C = act( A1 @ W1 [+ A2 @ W2] + bias )   (means pre-folded in gathers)
// KT=16 per stage, 2 stages: global loads for stage s+1 overlap compute of s,
// one barrier per stage.
// ---------------------------------------------------------------------------
template<int K1, int K2, int HO, bool RELU>
__device__ __forceinline__ void mm_body(const float* A1, const float* A2,
                                        const float* W1, const float* W2,
                                        const float* bias, float* C, int n) {
    constexpr int MT   = 128;
    constexpr int KT   = 16;
    constexpr int KTOT = K1 + K2;
    constexpr int NST  = KTOT / KT;
    constexpr int AS   = MT + 4;
    constexpr int NTHR = (HO / 8) * (MT / 8);

    __shared__ __align__(16) float shA[2][KT * AS];   // 2 x 8.45 KB
    __shared__ __align__(16) float shW[2][KT * HO];   // 2 x 8 KB (HO=128)

    const int tid  = threadIdx.x;
    const int tx   = tid % (HO / 8);
    const int ty   = tid / (HO / 8);
    const int row0 = blockIdx.x * MT;

    unsigned long long acc2[8][4];
#pragma unroll
    for (int r = 0; r < 8; ++r)
#pragma unroll
        for (int c = 0; c < 4; ++c) acc2[r][c] = 0ull;

    // Stage loader: global -> smem buffer `buf` for k-range [s*KT, s*KT+KT)
    auto load_stage = [&](int buf, int s) {
        const int kt = s * KT;
        const float* Wsrc = (kt < K1) ? (W1 + kt * HO) : (W2 + (kt - K1) * HO);
#pragma unroll
        for (int i = tid * 4; i < KT * HO; i += NTHR * 4)
            *reinterpret_cast<float4*>(&shW[buf][i]) =
                *reinterpret_cast<const float4*>(&Wsrc[i]);
        const float* Asrc;
        int kbase, KA;
        if (kt < K1) { Asrc = A1; kbase = kt;      KA = K1; }
        else         { Asrc = A2; kbase = kt - K1; KA = (K2 > 0) ? K2 : 1; }
#pragma unroll
        for (int i = tid; i < MT * (KT / 4); i += NTHR) {
            int r   = i / (KT / 4);
            int lk4 = i - r * (KT / 4);
            int gr  = row0 + r;
            float4 v = make_float4(0.f, 0.f, 0.f, 0.f);
            if (gr < n)
                v = *reinterpret_cast<const float4*>(&Asrc[gr * KA + kbase + lk4 * 4]);
            shA[buf][(lk4 * 4 + 0) * AS + r] = v.x;
            shA[buf][(lk4 * 4 + 1) * AS + r] = v.y;
            shA[buf][(lk4 * 4 + 2) * AS + r] = v.z;
            shA[buf][(lk4 * 4 + 3) * AS + r] = v.w;
        }
    };

    load_stage(0, 0);
    __syncthreads();

    for (int s = 0; s < NST; ++s) {
        const int cur = s & 1;
        if (s + 1 < NST) load_stage(cur ^ 1, s + 1);

        const float* shWt = &shW[cur][tx * 8];
        const float* shAt = &shA[cur][ty * 8];

        // register-pipelined inner loop over KT k-steps
        ulonglong2 wq0 = *reinterpret_cast<const ulonglong2*>(&shWt[0]);
        ulonglong2 wq1 = *reinterpret_cast<const ulonglong2*>(&shWt[4]);
        float4 a0 = *reinterpret_cast<const float4*>(&shAt[0]);
        float4 a1 = *reinterpret_cast<const float4*>(&shAt[4]);
#pragma unroll
        for (int k = 0; k < KT; ++k) {
            const int kn = (k + 1 < KT) ? (k + 1) : k;
            ulonglong2 nw0 = *reinterpret_cast<const ulonglong2*>(&shWt[kn * HO]);
            ulonglong2 nw1 = *reinterpret_cast<const ulonglong2*>(&shWt[kn * HO + 4]);
            float4 na0 = *reinterpret_cast<const float4*>(&shAt[kn * AS]);
            float4 na1 = *reinterpret_cast<const float4*>(&shAt[kn * AS + 4]);

            float av[8] = {a0.x, a0.y, a0.z, a0.w, a1.x, a1.y, a1.z, a1.w};
            unsigned long long ap[8];
#pragma unroll
            for (int r = 0; r < 8; ++r) ap[r] = pack2(av[r], av[r]);
#pragma unroll
            for (int r = 0; r < 8; ++r) {
                acc2[r][0] = fma2(ap[r], wq0.x, acc2[r][0]);
                acc2[r][1] = fma2(ap[r], wq0.y, acc2[r][1]);
                acc2[r][2] = fma2(ap[r], wq1.x, acc2[r][2]);
                acc2[r][3] = fma2(ap[r], wq1.y, acc2[r][3]);
            }
            wq0 = nw0; wq1 = nw1; a0 = na0; a1 = na1;
        }
        __syncthreads();
    }

    float4 b0 = *reinterpret_cast<const float4*>(&bias[tx * 8]);
    float4 b1 = *reinterpret_cast<const float4*>(&bias[tx * 8 + 4]);
    float bv[8] = {b0.x, b0.y, b0.z, b0.w, b1.x, b1.y, b1.z, b1.w};
#pragma unroll
    for (int r = 0; r < 8; ++r) {
        int gr = row0 + ty * 8 + r;
        if (gr < n) {
            float o[8];
#pragma unroll
            for (int c = 0; c < 4; ++c)
                unpack2(o[2 * c], o[2 * c + 1], acc2[r][c]);
#pragma unroll
            for (int c = 0; c < 8; ++c) {
                o[c] += bv[c];
                if (RELU) o[c] = fmaxf(o[c], 0.0f);
            }
            *reinterpret_cast<float4*>(&C[gr * HO + tx * 8]) =
                make_float4(o[0], o[1], o[2], o[3]);
            *reinterpret_cast<float4*>(&C[gr * HO + tx * 8 + 4]) =
                make_float4(o[4], o[5], o[6], o[7]);
        }
    }
}

__global__ void __launch_bounds__(256, 2)
kmm_one(const float* __restrict__ xin,
        const float* __restrict__ W1l,
        const float* __restrict__ W1r,
        const float* __restrict__ b1, int n) {
    mm_body<64, 64, 128, true>(s_agA, xin, W1l, W1r, b1, s_t1, n);
}
__global__ void __launch_bounds__(256, 2)
kmm_two(const float* __restrict__ Wlin1,
        const float* __restrict__ blin1, int n) {
    mm_body<128, 0, 128, true>(s_t1, nullptr, Wlin1, nullptr, blin1, s_t2, n);
}
__global__ void __launch_bounds__(256, 2)
kmm_three(const float* __restrict__ W2l,
          const float* __restrict__ W2r,
          const float* __restrict__ b2, int n) {
    mm_body<128, 128, 128, true>(s_agB, s_t2, W2l, W2r, b2, s_t3, n);
}
__global__ void __launch_bounds__(128, 2)
kmm_four(const float* __restrict__ Wlin2,
         const float* __restrict__ blin2,
         float* __restrict__ outp, int n) {
    mm_body<128, 0, 64, false>(s_t3, nullptr, Wlin2, nullptr, blin2, outp, n);
}

// ---------------------------------------------------------------------------
// Launch. Inputs (metadata order): x, edge_index, W1l, b1, W1r, Wlin1, blin1,
//                                  W2l, b2, W2r, Wlin2, blin2
// ---------------------------------------------------------------------------
extern "C" void kernel_launch(void* const* d_in, const int* in_sizes, int n_in,
                              void* d_out, int out_size) {
    const float* xin   = (const float*)d_in[0];
    const int*   eidx  = (const int*)d_in[1];
    const float* W1l   = (const float*)d_in[2];
    const float* b1    = (const float*)d_in[3];
    const float* W1r   = (const float*)d_in[4];
    const float* Wlin1 = (const float*)d_in[5];
    const float* blin1 = (const float*)d_in[6];
    const float* W2l   = (const float*)d_in[7];
    const float* b2    = (const float*)d_in[8];
    const float* W2r   = (const float*)d_in[9];
    const float* Wlin2 = (const float*)d_in[10];
    const float* blin2 = (const float*)d_in[11];
    float*       outp  = (float*)d_out;

    const int n = in_sizes[0] / P_D;   // 100000
    const int E = in_sizes[1] / 2;     // 1600000

    // --- CSR build (once; shared by both layers) ---
    kcsr_zero<<<(P_N + 256) / 256, 256>>>();
    kcsr_hist<<<(E + 255) / 256, 256>>>(eidx, E);
    kcsr_scan<<<1, 1024>>>();
    kcsr_fill<<<(E + 255) / 256, 256>>>(eidx, E);

    const int nblk  = (n + 127) / 128;
    const int nblkG = (n + 7) / 8;

    // Layer 1: gather + fused GEMM
    kg_one<<<nblkG, 256>>>(reinterpret_cast<const float2*>(xin));
    kmm_one<<<nblk, 256>>>(xin, W1l, W1r, b1, n);
    kmm_two<<<nblk, 256>>>(Wlin1, blin1, n);

    // Layer 2: gather + fused GEMM
    kg_two<<<nblkG, 256>>>(0);
    kmm_three<<<nblk, 256>>>(W2l, W2r, b2, n);
    kmm_four<<<nblk, 128>>>(Wlin2, blin2, outp, n);
}

// round 13
// speedup vs baseline: 2.3769x; 1.3455x over previous
#include <cuda_runtime.h>
#include <cstdint>

// Problem constants (fixed by the dataset)
#define P_N 100000
#define P_E 1600000
#define P_D 64
#define P_H 128
#define P_O 64

// Scratch: __device__ globals, only ever touched from device code.
__device__ float s_agA[P_N * P_D];     // layer-1 neighbor means  (25.6 MB)
__device__ float s_t1 [P_N * P_H];     // h1                      (51.2 MB)
__device__ float s_t2 [P_N * P_H];     // h2                      (51.2 MB)
__device__ float s_agB[P_N * P_H];     // layer-2 neighbor means  (51.2 MB)
__device__ float s_t3 [P_N * P_H];     // h3                      (51.2 MB)
// CSR scratch
__device__ int   g_ecnt  [P_N + 1];
__device__ int   g_rowptr[P_N + 1];
__device__ int   g_cursor[P_N + 1];
__device__ int   g_srcs  [P_E];

// ---------------------------------------------------------------------------
// tf32 helpers
// ---------------------------------------------------------------------------
__device__ __forceinline__ unsigned f2tf(float f) {
    unsigned u;
    asm("cvt.rna.tf32.f32 %0, %1;" : "=r"(u) : "f"(f));
    return u;
}
__device__ __forceinline__ void mma_tf32(float& d0, float& d1, float& d2, float& d3,
                                         unsigned a0, unsigned a1, unsigned a2, unsigned a3,
                                         unsigned b0, unsigned b1) {
    asm volatile(
        "mma.sync.aligned.m16n8k8.row.col.f32.tf32.tf32.f32 "
        "{%0,%1,%2,%3}, {%4,%5,%6,%7}, {%8,%9}, {%0,%1,%2,%3};"
        : "+f"(d0), "+f"(d1), "+f"(d2), "+f"(d3)
        : "r"(a0), "r"(a1), "r"(a2), "r"(a3), "r"(b0), "r"(b1));
}

// ---------------------------------------------------------------------------
// CSR build
// ---------------------------------------------------------------------------
__global__ void kcsr_zero() {
    int i = blockIdx.x * blockDim.x + threadIdx.x;
    if (i <= P_N) g_ecnt[i] = 0;
}
__global__ void kcsr_hist(const int* __restrict__ ei, int E) {
    int e = blockIdx.x * blockDim.x + threadIdx.x;
    if (e >= E) return;
    atomicAdd(&g_ecnt[ei[E + e]], 1);
}
__global__ void kcsr_scan() {
    __shared__ int part[1024];
    const int tid   = threadIdx.x;
    const int chunk = (P_N + 1023) / 1024;
    int lo = tid * chunk;
    int hi = lo + chunk; if (hi > P_N) hi = P_N;
    if (lo > P_N) lo = P_N;
    int s = 0;
    for (int i = lo; i < hi; ++i) s += g_ecnt[i];
    part[tid] = s;
    __syncthreads();
    for (int off = 1; off < 1024; off <<= 1) {
        int v = 0;
        if (tid >= off) v = part[tid - off];
        __syncthreads();
        if (tid >= off) part[tid] += v;
        __syncthreads();
    }
    int run = part[tid] - s;
    for (int i = lo; i < hi; ++i) {
        g_rowptr[i] = run;
        g_cursor[i] = run;
        run += g_ecnt[i];
    }
    if (hi == P_N) g_rowptr[P_N] = run;
}
__global__ void kcsr_fill(const int* __restrict__ ei, int E) {
    int e = blockIdx.x * blockDim.x + threadIdx.x;
    if (e >= E) return;
    int dst = ei[E + e];
    int pos = atomicAdd(&g_cursor[dst], 1);
    g_srcs[pos] = ei[e];
}

// ---------------------------------------------------------------------------
// Gather layer 1: s_agA[i] = mean over CSR row i of x[src]  (D=64).
// ---------------------------------------------------------------------------
__global__ void kg_one(const float2* __restrict__ x2) {
    int w    = (blockIdx.x * blockDim.x + threadIdx.x) >> 5;
    int lane = threadIdx.x & 31;
    if (w >= P_N) return;
    int lo = g_rowptr[w], hi = g_rowptr[w + 1];
    float ax0 = 0.f, ay0 = 0.f, ax1 = 0.f, ay1 = 0.f;
    int e = lo;
    for (; e + 1 < hi; e += 2) {
        int s0 = g_srcs[e], s1 = g_srcs[e + 1];
        float2 v0 = x2[s0 * 32 + lane];
        float2 v1 = x2[s1 * 32 + lane];
        ax0 += v0.x; ay0 += v0.y;
        ax1 += v1.x; ay1 += v1.y;
    }
    if (e < hi) {
        float2 v = x2[g_srcs[e] * 32 + lane];
        ax0 += v.x; ay0 += v.y;
    }
    int deg = hi - lo;
    float inv = (deg > 0) ? (1.0f / (float)deg) : 1.0f;
    float2 o;
    o.x = (ax0 + ax1) * inv;
    o.y = (ay0 + ay1) * inv;
    reinterpret_cast<float2*>(s_agA)[w * 32 + lane] = o;
}

// ---------------------------------------------------------------------------
// Gather layer 2: s_agB[i] = mean over CSR row i of s_t2[src]  (H=128).
// ---------------------------------------------------------------------------
__global__ void kg_two(int dummy) {
    int w    = (blockIdx.x * blockDim.x + threadIdx.x) >> 5;
    int lane = threadIdx.x & 31;
    if (w >= P_N) return;
    int lo = g_rowptr[w], hi = g_rowptr[w + 1];
    const float4* h4 = reinterpret_cast<const float4*>(s_t2);
    float a0[4] = {0.f, 0.f, 0.f, 0.f};
    float a1[4] = {0.f, 0.f, 0.f, 0.f};
    int e = lo;
    for (; e + 1 < hi; e += 2) {
        int s0 = g_srcs[e], s1 = g_srcs[e + 1];
        float4 v0 = h4[s0 * 32 + lane];
        float4 v1 = h4[s1 * 32 + lane];
        a0[0] += v0.x; a0[1] += v0.y; a0[2] += v0.z; a0[3] += v0.w;
        a1[0] += v1.x; a1[1] += v1.y; a1[2] += v1.z; a1[3] += v1.w;
    }
    if (e < hi) {
        float4 v = h4[g_srcs[e] * 32 + lane];
        a0[0] += v.x; a0[1] += v.y; a0[2] += v.z; a0[3] += v.w;
    }
    int deg = hi - lo;
    float inv = (deg > 0) ? (1.0f / (float)deg) : 1.0f;
    float4 o;
    o.x = (a0[0] + a1[0]) * inv;
    o.y = (a0[1] + a1[1]) * inv;
    o.z = (a0[2] + a1[2]) * inv;
    o.w = (a0[3] + a1[3]) * inv;
    reinterpret_cast<float4*>(s_agB)[w * 32 + lane] = o;
}

// ---------------------------------------------------------------------------
// TF32 tensor-core GEMM: C = act( A1 @ W1 [+ A2 @ W2] + bias )
// Block tile 128 x HO; 8 warps as 4(M) x 2(N); warp tile 32 x HO/2.
// mma.sync.m16n8k8 tf32, fp32 accumulate. KT=32 k-chunks staged in smem
// (tf32-converted), fragment loads bank-conflict-free by padding.
// ---------------------------------------------------------------------------
template<int K1, int K2, int HO, bool RELU>
__device__ __forceinline__ void mm_body(const float* A1, const float* A2,
                                        const float* W1, const float* W2,
                                        const float* bias, float* C, int n) {
    constexpr int MT   = 128;
    constexpr int KT   = 32;
    constexpr int KTOT = K1 + K2;
    constexpr int AS   = KT + 4;        // 36: A row stride (words). bank=(4g+t)%32 distinct
    constexpr int BS   = HO + 8;        // W row stride. bank=(8t+g)%32 distinct
    constexpr int NWT  = HO / 2;        // warp N tile
    constexpr int NJ   = NWT / 8;       // n8 tiles per warp

    __shared__ __align__(16) unsigned shA[MT * AS];   // tf32 A, row-major [MT][KT]
    __shared__ __align__(16) unsigned shB[KT * BS];   // tf32 W, row-major [KT][HO]

    const int tid   = threadIdx.x;
    const int lane  = tid & 31;
    const int warp  = tid >> 5;
    const int warpM = warp & 3;         // 0..3 -> M offset
    const int warpN = warp >> 2;        // 0..1 -> N offset
    const int g     = lane >> 2;        // group id (rows)
    const int t     = lane & 3;         // thread-in-group (k / out col pairs)
    const int row0  = blockIdx.x * MT;

    float acc[2][NJ][4];
#pragma unroll
    for (int i = 0; i < 2; ++i)
#pragma unroll
        for (int j = 0; j < NJ; ++j)
#pragma unroll
            for (int c = 0; c < 4; ++c) acc[i][j][c] = 0.0f;

    for (int kt = 0; kt < KTOT; kt += KT) {
        // --- stage W chunk [KT x HO] as tf32 ---
        const float* Wsrc = (kt < K1) ? (W1 + kt * HO) : (W2 + (kt - K1) * HO);
#pragma unroll
        for (int i = tid * 4; i < KT * HO; i += 1024) {
            float4 v = *reinterpret_cast<const float4*>(&Wsrc[i]);
            int row = i / HO, col = i - row * HO;
            uint4 u = make_uint4(f2tf(v.x), f2tf(v.y), f2tf(v.z), f2tf(v.w));
            *reinterpret_cast<uint4*>(&shB[row * BS + col]) = u;
        }
        // --- stage A chunk [MT x KT] as tf32 (row-major) ---
        const float* Asrc;
        int kbase, KA;
        if (kt < K1) { Asrc = A1; kbase = kt;      KA = K1; }
        else         { Asrc = A2; kbase = kt - K1; KA = (K2 > 0) ? K2 : 1; }
#pragma unroll
        for (int i = tid; i < MT * (KT / 4); i += 256) {
            int r   = i >> 3;           // / (KT/4)
            int lk4 = i & 7;
            int gr  = row0 + r;
            float4 v = make_float4(0.f, 0.f, 0.f, 0.f);
            if (gr < n)
                v = *reinterpret_cast<const float4*>(&Asrc[gr * KA + kbase + lk4 * 4]);
            uint4 u = make_uint4(f2tf(v.x), f2tf(v.y), f2tf(v.z), f2tf(v.w));
            *reinterpret_cast<uint4*>(&shA[r * AS + lk4 * 4]) = u;
        }
        __syncthreads();

        // --- 4 k8 steps of mma ---
#pragma unroll
        for (int k8 = 0; k8 < KT / 8; ++k8) {
            const int kb = k8 * 8;
            // A fragments for the two m16 tiles of this warp
            unsigned af[2][4];
#pragma unroll
            for (int i16 = 0; i16 < 2; ++i16) {
                int m0 = warpM * 32 + i16 * 16;
                const unsigned* base = &shA[(m0 + g) * AS + kb + t];
                af[i16][0] = base[0];
                af[i16][1] = base[8 * AS];
                af[i16][2] = base[4];
                af[i16][3] = base[8 * AS + 4];
            }
#pragma unroll
            for (int j = 0; j < NJ; ++j) {
                int n0 = warpN * NWT + j * 8;
                unsigned b0 = shB[(kb + t) * BS + n0 + g];
                unsigned b1 = shB[(kb + t + 4) * BS + n0 + g];
#pragma unroll
                for (int i16 = 0; i16 < 2; ++i16)
                    mma_tf32(acc[i16][j][0], acc[i16][j][1],
                             acc[i16][j][2], acc[i16][j][3],
                             af[i16][0], af[i16][1], af[i16][2], af[i16][3],
                             b0, b1);
            }
        }
        __syncthreads();
    }

    // --- epilogue: bias + relu, float2 stores ---
#pragma unroll
    for (int i16 = 0; i16 < 2; ++i16) {
        int rA = row0 + warpM * 32 + i16 * 16 + g;
        int rB = rA + 8;
#pragma unroll
        for (int j = 0; j < NJ; ++j) {
            int col = warpN * NWT + j * 8 + 2 * t;
            float2 bv = *reinterpret_cast<const float2*>(&bias[col]);
            if (rA < n) {
                float2 o;
                o.x = acc[i16][j][0] + bv.x;
                o.y = acc[i16][j][1] + bv.y;
                if (RELU) { o.x = fmaxf(o.x, 0.f); o.y = fmaxf(o.y, 0.f); }
                *reinterpret_cast<float2*>(&C[rA * HO + col]) = o;
            }
            if (rB < n) {
                float2 o;
                o.x = acc[i16][j][2] + bv.x;
                o.y = acc[i16][j][3] + bv.y;
                if (RELU) { o.x = fmaxf(o.x, 0.f); o.y = fmaxf(o.y, 0.f); }
                *reinterpret_cast<float2*>(&C[rB * HO + col]) = o;
            }
        }
    }
}

__global__ void __launch_bounds__(256, 2)
kmm_one(const float* __restrict__ xin,
        const float* __restrict__ W1l,
        const float* __restrict__ W1r,
        const float* __restrict__ b1, int n) {
    mm_body<64, 64, 128, true>(s_agA, xin, W1l, W1r, b1, s_t1, n);
}
__global__ void __launch_bounds__(256, 2)
kmm_two(const float* __restrict__ Wlin1,
        const float* __restrict__ blin1, int n) {
    mm_body<128, 0, 128, true>(s_t1, nullptr, Wlin1, nullptr, blin1, s_t2, n);
}
__global__ void __launch_bounds__(256, 2)
kmm_three(const float* __restrict__ W2l,
          const float* __restrict__ W2r,
          const float* __restrict__ b2, int n) {
    mm_body<128, 128, 128, true>(s_agB, s_t2, W2l, W2r, b2, s_t3, n);
}
__global__ void __launch_bounds__(256, 2)
kmm_four(const float* __restrict__ Wlin2,
         const float* __restrict__ blin2,
         float* __restrict__ outp, int n) {
    mm_body<128, 0, 64, false>(s_t3, nullptr, Wlin2, nullptr, blin2, outp, n);
}

// ---------------------------------------------------------------------------
// Launch. Inputs (metadata order): x, edge_index, W1l, b1, W1r, Wlin1, blin1,
//                                  W2l, b2, W2r, Wlin2, blin2
// ---------------------------------------------------------------------------
extern "C" void kernel_launch(void* const* d_in, const int* in_sizes, int n_in,
                              void* d_out, int out_size) {
    const float* xin   = (const float*)d_in[0];
    const int*   eidx  = (const int*)d_in[1];
    const float* W1l   = (const float*)d_in[2];
    const float* b1    = (const float*)d_in[3];
    const float* W1r   = (const float*)d_in[4];
    const float* Wlin1 = (const float*)d_in[5];
    const float* blin1 = (const float*)d_in[6];
    const float* W2l   = (const float*)d_in[7];
    const float* b2    = (const float*)d_in[8];
    const float* W2r   = (const float*)d_in[9];
    const float* Wlin2 = (const float*)d_in[10];
    const float* blin2 = (const float*)d_in[11];
    float*       outp  = (float*)d_out;

    const int n = in_sizes[0] / P_D;   // 100000
    const int E = in_sizes[1] / 2;     // 1600000

    // --- CSR build (once; shared by both layers) ---
    kcsr_zero<<<(P_N + 256) / 256, 256>>>();
    kcsr_hist<<<(E + 255) / 256, 256>>>(eidx, E);
    kcsr_scan<<<1, 1024>>>();
    kcsr_fill<<<(E + 255) / 256, 256>>>(eidx, E);

    const int nblk  = (n + 127) / 128;
    const int nblkG = (n + 7) / 8;

    // Layer 1: gather + fused GEMM
    kg_one<<<nblkG, 256>>>(reinterpret_cast<const float2*>(xin));
    kmm_one<<<nblk, 256>>>(xin, W1l, W1r, b1, n);
    kmm_two<<<nblk, 256>>>(Wlin1, blin1, n);

    // Layer 2: gather + fused GEMM
    kg_two<<<nblkG, 256>>>(0);
    kmm_three<<<nblk, 256>>>(W2l, W2r, b2, n);
    kmm_four<<<nblk, 256>>>(Wlin2, blin2, outp, n);
}

// round 14
// speedup vs baseline: 2.6068x; 1.0967x over previous
#include <cuda_runtime.h>
#include <cstdint>

// Problem constants (fixed by the dataset)
#define P_N 100000
#define P_E 1600000
#define P_D 64
#define P_H 128
#define P_O 64

// Scratch: __device__ globals, only ever touched from device code.
__device__ float s_agA[P_N * P_D];     // layer-1 neighbor means  (25.6 MB)
__device__ float s_t2 [P_N * P_H];     // h2                      (51.2 MB)
__device__ float s_agB[P_N * P_H];     // layer-2 neighbor means  (51.2 MB)
// CSR scratch
__device__ int   g_ecnt  [P_N + 1];
__device__ int   g_rowptr[P_N + 1];
__device__ int   g_cursor[P_N + 1];
__device__ int   g_srcs  [P_E];

// ---------------------------------------------------------------------------
// tf32 helpers
// ---------------------------------------------------------------------------
__device__ __forceinline__ unsigned f2tf(float f) {
    unsigned u;
    asm("cvt.rna.tf32.f32 %0, %1;" : "=r"(u) : "f"(f));
    return u;
}
__device__ __forceinline__ void mma_tf32(float& d0, float& d1, float& d2, float& d3,
                                         unsigned a0, unsigned a1, unsigned a2, unsigned a3,
                                         unsigned b0, unsigned b1) {
    asm volatile(
        "mma.sync.aligned.m16n8k8.row.col.f32.tf32.tf32.f32 "
        "{%0,%1,%2,%3}, {%4,%5,%6,%7}, {%8,%9}, {%0,%1,%2,%3};"
        : "+f"(d0), "+f"(d1), "+f"(d2), "+f"(d3)
        : "r"(a0), "r"(a1), "r"(a2), "r"(a3), "r"(b0), "r"(b1));
}

// ---------------------------------------------------------------------------
// CSR build
// ---------------------------------------------------------------------------
__global__ void kcsr_zero() {
    int i = blockIdx.x * blockDim.x + threadIdx.x;
    if (i <= P_N) g_ecnt[i] = 0;
}
__global__ void kcsr_hist(const int* __restrict__ ei, int E) {
    int e = blockIdx.x * blockDim.x + threadIdx.x;
    if (e >= E) return;
    atomicAdd(&g_ecnt[ei[E + e]], 1);
}
__global__ void kcsr_scan() {
    __shared__ int part[1024];
    const int tid   = threadIdx.x;
    const int chunk = (P_N + 1023) / 1024;
    int lo = tid * chunk;
    int hi = lo + chunk; if (hi > P_N) hi = P_N;
    if (lo > P_N) lo = P_N;
    int s = 0;
    for (int i = lo; i < hi; ++i) s += g_ecnt[i];
    part[tid] = s;
    __syncthreads();
    for (int off = 1; off < 1024; off <<= 1) {
        int v = 0;
        if (tid >= off) v = part[tid - off];
        __syncthreads();
        if (tid >= off) part[tid] += v;
        __syncthreads();
    }
    int run = part[tid] - s;
    for (int i = lo; i < hi; ++i) {
        g_rowptr[i] = run;
        g_cursor[i] = run;
        run += g_ecnt[i];
    }
    if (hi == P_N) g_rowptr[P_N] = run;
}
__global__ void kcsr_fill(const int* __restrict__ ei, int E) {
    int e = blockIdx.x * blockDim.x + threadIdx.x;
    if (e >= E) return;
    int dst = ei[E + e];
    int pos = atomicAdd(&g_cursor[dst], 1);
    g_srcs[pos] = ei[e];
}

// ---------------------------------------------------------------------------
// Gather layer 1: s_agA[i] = mean over CSR row i of x[src]  (D=64).
// ---------------------------------------------------------------------------
__global__ void kg_one(const float2* __restrict__ x2) {
    int w    = (blockIdx.x * blockDim.x + threadIdx.x) >> 5;
    int lane = threadIdx.x & 31;
    if (w >= P_N) return;
    int lo = g_rowptr[w], hi = g_rowptr[w + 1];
    float ax0 = 0.f, ay0 = 0.f, ax1 = 0.f, ay1 = 0.f;
    int e = lo;
    for (; e + 1 < hi; e += 2) {
        int s0 = g_srcs[e], s1 = g_srcs[e + 1];
        float2 v0 = x2[s0 * 32 + lane];
        float2 v1 = x2[s1 * 32 + lane];
        ax0 += v0.x; ay0 += v0.y;
        ax1 += v1.x; ay1 += v1.y;
    }
    if (e < hi) {
        float2 v = x2[g_srcs[e] * 32 + lane];
        ax0 += v.x; ay0 += v.y;
    }
    int deg = hi - lo;
    float inv = (deg > 0) ? (1.0f / (float)deg) : 1.0f;
    float2 o;
    o.x = (ax0 + ax1) * inv;
    o.y = (ay0 + ay1) * inv;
    reinterpret_cast<float2*>(s_agA)[w * 32 + lane] = o;
}

// ---------------------------------------------------------------------------
// Gather layer 2: s_agB[i] = mean over CSR row i of s_t2[src]  (H=128).
// ---------------------------------------------------------------------------
__global__ void kg_two(int dummy) {
    int w    = (blockIdx.x * blockDim.x + threadIdx.x) >> 5;
    int lane = threadIdx.x & 31;
    if (w >= P_N) return;
    int lo = g_rowptr[w], hi = g_rowptr[w + 1];
    const float4* h4 = reinterpret_cast<const float4*>(s_t2);
    float a0[4] = {0.f, 0.f, 0.f, 0.f};
    float a1[4] = {0.f, 0.f, 0.f, 0.f};
    int e = lo;
    for (; e + 1 < hi; e += 2) {
        int s0 = g_srcs[e], s1 = g_srcs[e + 1];
        float4 v0 = h4[s0 * 32 + lane];
        float4 v1 = h4[s1 * 32 + lane];
        a0[0] += v0.x; a0[1] += v0.y; a0[2] += v0.z; a0[3] += v0.w;
        a1[0] += v1.x; a1[1] += v1.y; a1[2] += v1.z; a1[3] += v1.w;
    }
    if (e < hi) {
        float4 v = h4[g_srcs[e] * 32 + lane];
        a0[0] += v.x; a0[1] += v.y; a0[2] += v.z; a0[3] += v.w;
    }
    int deg = hi - lo;
    float inv = (deg > 0) ? (1.0f / (float)deg) : 1.0f;
    float4 o;
    o.x = (a0[0] + a1[0]) * inv;
    o.y = (a0[1] + a1[1]) * inv;
    o.z = (a0[2] + a1[2]) * inv;
    o.w = (a0[3] + a1[3]) * inv;
    reinterpret_cast<float4*>(s_agB)[w * 32 + lane] = o;
}

// ---------------------------------------------------------------------------
// Fused two-stage TF32 tensor-core GEMM:
//   phase1: Hrow = relu( A1 @ W1 [+ A2 @ W2] + b1 )        (HO1 = 128)
//   phase2: C    = act ( Hrow @ W3 + b3 )                   (HO2 = 128 or 64)
// h-tile never leaves the SM: written tf32 to smem, consumed by phase 2.
// Block tile 128 rows; 8 warps 4(M) x 2(N); mma.sync m16n8k8 tf32.
// Dynamic smem: shH 128x132 + shA 128x36 + shB 32x136 (words) = 101 KB.
// ---------------------------------------------------------------------------
template<int K1, int K2, int HO2, bool RELU2>
__device__ __forceinline__ void fused_body(const float* A1, const float* A2,
                                           const float* W1, const float* W2,
                                           const float* b1v,
                                           const float* W3, const float* b3v,
                                           float* C, int n) {
    constexpr int MT   = 128;
    constexpr int KT   = 32;
    constexpr int KTOT = K1 + K2;
    constexpr int HO1  = 128;
    constexpr int AS   = KT + 4;      // 36
    constexpr int BS   = HO1 + 8;     // 136
    constexpr int HS   = HO1 + 4;     // 132  (bank (4g+t)%32 distinct)
    constexpr int BS2  = HO2 + 8;
    constexpr int NJ1  = (HO1 / 2) / 8;   // 8
    constexpr int NJ2  = (HO2 / 2) / 8;   // 8 or 4

    extern __shared__ __align__(16) unsigned dsm[];
    unsigned* shH = dsm;                          // MT*HS
    unsigned* shA = dsm + MT * HS;                // MT*AS
    unsigned* shB = dsm + MT * HS + MT * AS;      // KT*BS (>= KT*BS2)

    const int tid   = threadIdx.x;
    const int lane  = tid & 31;
    const int warp  = tid >> 5;
    const int warpM = warp & 3;
    const int warpN = warp >> 2;
    const int g     = lane >> 2;
    const int t     = lane & 3;
    const int row0  = blockIdx.x * MT;

    // ============================ PHASE 1 ============================
    {
        float acc[2][NJ1][4];
#pragma unroll
        for (int i = 0; i < 2; ++i)
#pragma unroll
            for (int j = 0; j < NJ1; ++j)
#pragma unroll
                for (int c = 0; c < 4; ++c) acc[i][j][c] = 0.0f;

        for (int kt = 0; kt < KTOT; kt += KT) {
            const float* Wsrc = (kt < K1) ? (W1 + kt * HO1) : (W2 + (kt - K1) * HO1);
#pragma unroll
            for (int i = tid * 4; i < KT * HO1; i += 1024) {
                float4 v = *reinterpret_cast<const float4*>(&Wsrc[i]);
                int row = i / HO1, col = i - row * HO1;
                uint4 u = make_uint4(f2tf(v.x), f2tf(v.y), f2tf(v.z), f2tf(v.w));
                *reinterpret_cast<uint4*>(&shB[row * BS + col]) = u;
            }
            const float* Asrc;
            int kbase, KA;
            if (kt < K1) { Asrc = A1; kbase = kt;      KA = K1; }
            else         { Asrc = A2; kbase = kt - K1; KA = (K2 > 0) ? K2 : 1; }
#pragma unroll
            for (int i = tid; i < MT * (KT / 4); i += 256) {
                int r   = i >> 3;
                int lk4 = i & 7;
                int gr  = row0 + r;
                float4 v = make_float4(0.f, 0.f, 0.f, 0.f);
                if (gr < n)
                    v = *reinterpret_cast<const float4*>(&Asrc[gr * KA + kbase + lk4 * 4]);
                uint4 u = make_uint4(f2tf(v.x), f2tf(v.y), f2tf(v.z), f2tf(v.w));
                *reinterpret_cast<uint4*>(&shA[r * AS + lk4 * 4]) = u;
            }
            __syncthreads();

#pragma unroll
            for (int k8 = 0; k8 < KT / 8; ++k8) {
                const int kb = k8 * 8;
                unsigned af[2][4];
#pragma unroll
                for (int i16 = 0; i16 < 2; ++i16) {
                    int m0 = warpM * 32 + i16 * 16;
                    const unsigned* base = &shA[(m0 + g) * AS + kb + t];
                    af[i16][0] = base[0];
                    af[i16][1] = base[8 * AS];
                    af[i16][2] = base[4];
                    af[i16][3] = base[8 * AS + 4];
                }
#pragma unroll
                for (int j = 0; j < NJ1; ++j) {
                    int n0 = warpN * (HO1 / 2) + j * 8;
                    unsigned b0 = shB[(kb + t) * BS + n0 + g];
                    unsigned b1 = shB[(kb + t + 4) * BS + n0 + g];
#pragma unroll
                    for (int i16 = 0; i16 < 2; ++i16)
                        mma_tf32(acc[i16][j][0], acc[i16][j][1],
                                 acc[i16][j][2], acc[i16][j][3],
                                 af[i16][0], af[i16][1], af[i16][2], af[i16][3],
                                 b0, b1);
                }
            }
            __syncthreads();
        }

        // epilogue: bias + relu, tf32 into shH (tile-local; unconditional)
#pragma unroll
        for (int i16 = 0; i16 < 2; ++i16) {
            int rA = warpM * 32 + i16 * 16 + g;
            int rB = rA + 8;
#pragma unroll
            for (int j = 0; j < NJ1; ++j) {
                int col = warpN * (HO1 / 2) + j * 8 + 2 * t;
                float2 bv = *reinterpret_cast<const float2*>(&b1v[col]);
                shH[rA * HS + col]     = f2tf(fmaxf(acc[i16][j][0] + bv.x, 0.f));
                shH[rA * HS + col + 1] = f2tf(fmaxf(acc[i16][j][1] + bv.y, 0.f));
                shH[rB * HS + col]     = f2tf(fmaxf(acc[i16][j][2] + bv.x, 0.f));
                shH[rB * HS + col + 1] = f2tf(fmaxf(acc[i16][j][3] + bv.y, 0.f));
            }
        }
        __syncthreads();
    }

    // ============================ PHASE 2 ============================
    {
        float acc[2][NJ2][4];
#pragma unroll
        for (int i = 0; i < 2; ++i)
#pragma unroll
            for (int j = 0; j < NJ2; ++j)
#pragma unroll
                for (int c = 0; c < 4; ++c) acc[i][j][c] = 0.0f;

        for (int kt = 0; kt < HO1; kt += KT) {
            // stage W3 chunk [KT x HO2]
#pragma unroll
            for (int i = tid * 4; i < KT * HO2; i += 1024) {
                float4 v = *reinterpret_cast<const float4*>(&W3[kt * HO2 + i]);
                int row = i / HO2, col = i - row * HO2;
                uint4 u = make_uint4(f2tf(v.x), f2tf(v.y), f2tf(v.z), f2tf(v.w));
                *reinterpret_cast<uint4*>(&shB[row * BS2 + col]) = u;
            }
            __syncthreads();

#pragma unroll
            for (int k8 = 0; k8 < KT / 8; ++k8) {
                const int kb = k8 * 8;
                unsigned af[2][4];
#pragma unroll
                for (int i16 = 0; i16 < 2; ++i16) {
                    int m0 = warpM * 32 + i16 * 16;
                    const unsigned* base = &shH[(m0 + g) * HS + kt + kb + t];
                    af[i16][0] = base[0];
                    af[i16][1] = base[8 * HS];
                    af[i16][2] = base[4];
                    af[i16][3] = base[8 * HS + 4];
                }
#pragma unroll
                for (int j = 0; j < NJ2; ++j) {
                    int n0 = warpN * (HO2 / 2) + j * 8;
                    unsigned b0 = shB[(kb + t) * BS2 + n0 + g];
                    unsigned b1 = shB[(kb + t + 4) * BS2 + n0 + g];
#pragma unroll
                    for (int i16 = 0; i16 < 2; ++i16)
                        mma_tf32(acc[i16][j][0], acc[i16][j][1],
                                 acc[i16][j][2], acc[i16][j][3],
                                 af[i16][0], af[i16][1], af[i16][2], af[i16][3],
                                 b0, b1);
                }
            }
            __syncthreads();
        }

        // epilogue: bias (+relu) to global
#pragma unroll
        for (int i16 = 0; i16 < 2; ++i16) {
            int rA = row0 + warpM * 32 + i16 * 16 + g;
            int rB = rA + 8;
#pragma unroll
            for (int j = 0; j < NJ2; ++j) {
                int col = warpN * (HO2 / 2) + j * 8 + 2 * t;
                float2 bv = *reinterpret_cast<const float2*>(&b3v[col]);
                if (rA < n) {
                    float2 o;
                    o.x = acc[i16][j][0] + bv.x;
                    o.y = acc[i16][j][1] + bv.y;
                    if (RELU2) { o.x = fmaxf(o.x, 0.f); o.y = fmaxf(o.y, 0.f); }
                    *reinterpret_cast<float2*>(&C[rA * HO2 + col]) = o;
                }
                if (rB < n) {
                    float2 o;
                    o.x = acc[i16][j][2] + bv.x;
                    o.y = acc[i16][j][3] + bv.y;
                    if (RELU2) { o.x = fmaxf(o.x, 0.f); o.y = fmaxf(o.y, 0.f); }
                    *reinterpret_cast<float2*>(&C[rB * HO2 + col]) = o;
                }
            }
        }
    }
}

// Fused wrappers. Layer block 1: sage1 + lin1 (relu) -> s_t2.
__global__ void __launch_bounds__(256, 2)
kfusedA(const float* __restrict__ xin,
        const float* __restrict__ W1l, const float* __restrict__ W1r,
        const float* __restrict__ b1,
        const float* __restrict__ Wlin1, const float* __restrict__ blin1,
        int n) {
    fused_body<64, 64, 128, true>(s_agA, xin, W1l, W1r, b1, Wlin1, blin1, s_t2, n);
}
// Layer block 2: sage2 + lin2 (no relu) -> out.
__global__ void __launch_bounds__(256, 2)
kfusedB(const float* __restrict__ W2l, const float* __restrict__ W2r,
        const float* __restrict__ b2,
        const float* __restrict__ Wlin2, const float* __restrict__ blin2,
        float* __restrict__ outp, int n) {
    fused_body<128, 128, 64, false>(s_agB, s_t2, W2l, W2r, b2, Wlin2, blin2, outp, n);
}

// ---------------------------------------------------------------------------
// Launch. Inputs (metadata order): x, edge_index, W1l, b1, W1r, Wlin1, blin1,
//                                  W2l, b2, W2r, Wlin2, blin2
// ---------------------------------------------------------------------------
extern "C" void kernel_launch(void* const* d_in, const int* in_sizes, int n_in,
                              void* d_out, int out_size) {
    const float* xin   = (const float*)d_in[0];
    const int*   eidx  = (const int*)d_in[1];
    const float* W1l   = (const float*)d_in[2];
    const float* b1    = (const float*)d_in[3];
    const float* W1r   = (const float*)d_in[4];
    const float* Wlin1 = (const float*)d_in[5];
    const float* blin1 = (const float*)d_in[6];
    const float* W2l   = (const float*)d_in[7];
    const float* b2    = (const float*)d_in[8];
    const float* W2r   = (const float*)d_in[9];
    const float* Wlin2 = (const float*)d_in[10];
    const float* blin2 = (const float*)d_in[11];
    float*       outp  = (float*)d_out;

    const int n = in_sizes[0] / P_D;   // 100000
    const int E = in_sizes[1] / 2;     // 1600000

    // Dynamic smem: (128*132 + 128*36 + 32*136) * 4 = 103424 bytes
    const int SMEM_BYTES = (128 * 132 + 128 * 36 + 32 * 136) * 4;
    cudaFuncSetAttribute(kfusedA, cudaFuncAttributeMaxDynamicSharedMemorySize, SMEM_BYTES);
    cudaFuncSetAttribute(kfusedB, cudaFuncAttributeMaxDynamicSharedMemorySize, SMEM_BYTES);

    // --- CSR build (once; shared by both layers) ---
    kcsr_zero<<<(P_N + 256) / 256, 256>>>();
    kcsr_hist<<<(E + 255) / 256, 256>>>(eidx, E);
    kcsr_scan<<<1, 1024>>>();
    kcsr_fill<<<(E + 255) / 256, 256>>>(eidx, E);

    const int nblk  = (n + 127) / 128;
    const int nblkG = (n + 7) / 8;

    // Layer block 1: gather + fused (sage1 + lin1)
    kg_one<<<nblkG, 256>>>(reinterpret_cast<const float2*>(xin));
    kfusedA<<<nblk, 256, SMEM_BYTES>>>(xin, W1l, W1r, b1, Wlin1, blin1, n);

    // Layer block 2: gather + fused (sage2 + lin2)
    kg_two<<<nblkG, 256>>>(0);
    kfusedB<<<nblk, 256, SMEM_BYTES>>>(W2l, W2r, b2, Wlin2, blin2, outp, n);
}

// round 15
// speedup vs baseline: 2.9115x; 1.1169x over previous
#include <cuda_runtime.h>
#include <cstdint>

// Problem constants (fixed by the dataset)
#define P_N 100000
#define P_E 1600000
#define P_D 64
#define P_H 128
#define P_O 64

// Scratch: __device__ globals, only ever touched from device code.
__device__ float s_agA[P_N * P_D];     // layer-1 neighbor means  (25.6 MB)
__device__ float s_t2 [P_N * P_H];     // h2                      (51.2 MB)
__device__ float s_agB[P_N * P_H];     // layer-2 neighbor means  (51.2 MB)
// CSR scratch
__device__ int   g_ecnt  [P_N + 1];
__device__ int   g_rowptr[P_N + 1];
__device__ int   g_cursor[P_N + 1];
__device__ int   g_srcs  [P_E];

// ---------------------------------------------------------------------------
// tf32 / cp.async helpers
// ---------------------------------------------------------------------------
__device__ __forceinline__ unsigned f2tf(float f) {
    unsigned u;
    asm("cvt.rna.tf32.f32 %0, %1;" : "=r"(u) : "f"(f));
    return u;
}
__device__ __forceinline__ void mma_tf32(float& d0, float& d1, float& d2, float& d3,
                                         unsigned a0, unsigned a1, unsigned a2, unsigned a3,
                                         unsigned b0, unsigned b1) {
    asm volatile(
        "mma.sync.aligned.m16n8k8.row.col.f32.tf32.tf32.f32 "
        "{%0,%1,%2,%3}, {%4,%5,%6,%7}, {%8,%9}, {%0,%1,%2,%3};"
        : "+f"(d0), "+f"(d1), "+f"(d2), "+f"(d3)
        : "r"(a0), "r"(a1), "r"(a2), "r"(a3), "r"(b0), "r"(b1));
}
__device__ __forceinline__ void cp16(unsigned saddr, const void* g, int bytes) {
    asm volatile("cp.async.cg.shared.global [%0], [%1], 16, %2;"
                 :: "r"(saddr), "l"(g), "r"(bytes) : "memory");
}
#define CP_COMMIT() asm volatile("cp.async.commit_group;" ::: "memory")
#define CP_WAIT1()  asm volatile("cp.async.wait_group 1;" ::: "memory")
#define CP_WAIT0()  asm volatile("cp.async.wait_group 0;" ::: "memory")

// ---------------------------------------------------------------------------
// CSR build
// ---------------------------------------------------------------------------
__global__ void kcsr_zero() {
    int i = blockIdx.x * blockDim.x + threadIdx.x;
    if (i <= P_N) g_ecnt[i] = 0;
}
__global__ void kcsr_hist(const int* __restrict__ ei, int E) {
    int e = blockIdx.x * blockDim.x + threadIdx.x;
    if (e >= E) return;
    atomicAdd(&g_ecnt[ei[E + e]], 1);
}
__global__ void kcsr_scan() {
    __shared__ int part[1024];
    const int tid   = threadIdx.x;
    const int chunk = (P_N + 1023) / 1024;
    int lo = tid * chunk;
    int hi = lo + chunk; if (hi > P_N) hi = P_N;
    if (lo > P_N) lo = P_N;
    int s = 0;
    for (int i = lo; i < hi; ++i) s += g_ecnt[i];
    part[tid] = s;
    __syncthreads();
    for (int off = 1; off < 1024; off <<= 1) {
        int v = 0;
        if (tid >= off) v = part[tid - off];
        __syncthreads();
        if (tid >= off) part[tid] += v;
        __syncthreads();
    }
    int run = part[tid] - s;
    for (int i = lo; i < hi; ++i) {
        g_rowptr[i] = run;
        g_cursor[i] = run;
        run += g_ecnt[i];
    }
    if (hi == P_N) g_rowptr[P_N] = run;
}
__global__ void kcsr_fill(const int* __restrict__ ei, int E) {
    int e = blockIdx.x * blockDim.x + threadIdx.x;
    if (e >= E) return;
    int dst = ei[E + e];
    int pos = atomicAdd(&g_cursor[dst], 1);
    g_srcs[pos] = ei[e];
}

// ---------------------------------------------------------------------------
// Gather layer 1: s_agA[i] = mean over CSR row i of x[src]  (D=64).
// ---------------------------------------------------------------------------
__global__ void kg_one(const float2* __restrict__ x2) {
    int w    = (blockIdx.x * blockDim.x + threadIdx.x) >> 5;
    int lane = threadIdx.x & 31;
    if (w >= P_N) return;
    int lo = g_rowptr[w], hi = g_rowptr[w + 1];
    float ax0 = 0.f, ay0 = 0.f, ax1 = 0.f, ay1 = 0.f;
    int e = lo;
    for (; e + 1 < hi; e += 2) {
        int s0 = g_srcs[e], s1 = g_srcs[e + 1];
        float2 v0 = x2[s0 * 32 + lane];
        float2 v1 = x2[s1 * 32 + lane];
        ax0 += v0.x; ay0 += v0.y;
        ax1 += v1.x; ay1 += v1.y;
    }
    if (e < hi) {
        float2 v = x2[g_srcs[e] * 32 + lane];
        ax0 += v.x; ay0 += v.y;
    }
    int deg = hi - lo;
    float inv = (deg > 0) ? (1.0f / (float)deg) : 1.0f;
    float2 o;
    o.x = (ax0 + ax1) * inv;
    o.y = (ay0 + ay1) * inv;
    reinterpret_cast<float2*>(s_agA)[w * 32 + lane] = o;
}

// ---------------------------------------------------------------------------
// Gather layer 2: s_agB[i] = mean over CSR row i of s_t2[src]  (H=128).
// ---------------------------------------------------------------------------
__global__ void kg_two(int dummy) {
    int w    = (blockIdx.x * blockDim.x + threadIdx.x) >> 5;
    int lane = threadIdx.x & 31;
    if (w >= P_N) return;
    int lo = g_rowptr[w], hi = g_rowptr[w + 1];
    const float4* h4 = reinterpret_cast<const float4*>(s_t2);
    float a0[4] = {0.f, 0.f, 0.f, 0.f};
    float a1[4] = {0.f, 0.f, 0.f, 0.f};
    int e = lo;
    for (; e + 1 < hi; e += 2) {
        int s0 = g_srcs[e], s1 = g_srcs[e + 1];
        float4 v0 = h4[s0 * 32 + lane];
        float4 v1 = h4[s1 * 32 + lane];
        a0[0] += v0.x; a0[1] += v0.y; a0[2] += v0.z; a0[3] += v0.w;
        a1[0] += v1.x; a1[1] += v1.y; a1[2] += v1.z; a1[3] += v1.w;
    }
    if (e < hi) {
        float4 v = h4[g_srcs[e] * 32 + lane];
        a0[0] += v.x; a0[1] += v.y; a0[2] += v.z; a0[3] += v.w;
    }
    int deg = hi - lo;
    float inv = (deg > 0) ? (1.0f / (float)deg) : 1.0f;
    float4 o;
    o.x = (a0[0] + a1[0]) * inv;
    o.y = (a0[1] + a1[1]) * inv;
    o.z = (a0[2] + a1[2]) * inv;
    o.w = (a0[3] + a1[3]) * inv;
    reinterpret_cast<float4*>(s_agB)[w * 32 + lane] = o;
}

// ---------------------------------------------------------------------------
// Fused two-stage TF32 GEMM with cp.async double-buffered staging.
//   phase1: H = relu( A1 @ W1 [+ A2 @ W2] + b1 )   (HO1=128, tf32 h-tile in smem)
//   phase2: C = act ( H @ W3 + b3 )                 (HO2 = 128 or 64)
// Stage = KT=16 k-rows: raw fp32 via cp.async (zfill OOB), tf32 cvt at
// fragment load (ALU pipe, overlaps tensor pipe). Numerics identical to
// convert-at-store.
// Smem words: shH 128*132=16896, shA 2*128*20=5120, shB 2*16*136=4352.
// ---------------------------------------------------------------------------
template<int K1, int K2, int HO2, bool RELU2>
__device__ __forceinline__ void fused_body(const float* A1, const float* A2,
                                           const float* W1, const float* W2,
                                           const float* b1v,
                                           const float* W3, const float* b3v,
                                           float* C, int n) {
    constexpr int MT   = 128;
    constexpr int KT   = 16;
    constexpr int KTOT = K1 + K2;
    constexpr int NST1 = KTOT / KT;
    constexpr int NST2 = 128 / KT;
    constexpr int HO1  = 128;
    constexpr int AS   = KT + 4;        // 20  (banks (20g+t)%32 distinct)
    constexpr int BS   = HO1 + 8;       // 136 (banks (8t+g)%32 distinct)
    constexpr int HS   = HO1 + 4;       // 132
    constexpr int BS2  = HO2 + 8;
    constexpr int NJ1  = 8;
    constexpr int NJ2  = (HO2 / 2) / 8;
    constexpr int ABUF = MT * AS;       // 2560 words / buffer
    constexpr int BBUF = KT * BS;       // 2176 words / buffer (>= KT*BS2)

    extern __shared__ __align__(16) float dsm[];
    unsigned* shH = reinterpret_cast<unsigned*>(dsm);       // 16896 words
    float*    shA = dsm + MT * HS;                          // 2 x 2560
    float*    shB = dsm + MT * HS + 2 * ABUF;               // 2 x 2176

    const unsigned shA_s = (unsigned)__cvta_generic_to_shared(shA);
    const unsigned shB_s = (unsigned)__cvta_generic_to_shared(shB);

    const int tid   = threadIdx.x;
    const int lane  = tid & 31;
    const int warp  = tid >> 5;
    const int warpM = warp & 3;
    const int warpN = warp >> 2;
    const int g     = lane >> 2;
    const int t     = lane & 3;
    const int row0  = blockIdx.x * MT;

    // ---- phase 1 stage loader (cp.async raw fp32) ----
    auto load1 = [&](int buf, int s) {
        const int kt = s * KT;
        const float* Wsrc; int wkb;
        if (kt < K1) { Wsrc = W1; wkb = kt; } else { Wsrc = W2; wkb = kt - K1; }
        unsigned bb = shB_s + (unsigned)(buf * BBUF) * 4u;
#pragma unroll
        for (int i = tid; i < KT * (HO1 / 4); i += 256) {     // 512 chunks
            int row = i >> 5, c4 = i & 31;
            cp16(bb + (unsigned)(row * BS + c4 * 4) * 4u,
                 &Wsrc[(wkb + row) * HO1 + c4 * 4], 16);
        }
        const float* Asrc; int kbase, KA;
        if (kt < K1) { Asrc = A1; kbase = kt;      KA = K1; }
        else         { Asrc = A2; kbase = kt - K1; KA = (K2 > 0) ? K2 : 1; }
        unsigned ab = shA_s + (unsigned)(buf * ABUF) * 4u;
#pragma unroll
        for (int i = tid; i < MT * (KT / 4); i += 256) {      // 512 chunks
            int r = i >> 2, lk4 = i & 3;
            int gr = row0 + r;
            int ok = (gr < n);
            int grc = ok ? gr : 0;
            cp16(ab + (unsigned)(r * AS + lk4 * 4) * 4u,
                 &Asrc[(size_t)grc * KA + kbase + lk4 * 4], ok ? 16 : 0);
        }
    };

    // ============================ PHASE 1 ============================
    {
        float acc[2][NJ1][4];
#pragma unroll
        for (int i = 0; i < 2; ++i)
#pragma unroll
            for (int j = 0; j < NJ1; ++j)
#pragma unroll
                for (int c = 0; c < 4; ++c) acc[i][j][c] = 0.0f;

        load1(0, 0); CP_COMMIT();

        for (int s = 0; s < NST1; ++s) {
            const int buf = s & 1;
            if (s + 1 < NST1) { load1(buf ^ 1, s + 1); CP_COMMIT(); CP_WAIT1(); }
            else              { CP_WAIT0(); }
            __syncthreads();

            const float* sa = shA + buf * ABUF;
            const float* sb = shB + buf * BBUF;
#pragma unroll
            for (int k8 = 0; k8 < KT / 8; ++k8) {
                const int kb = k8 * 8;
                unsigned af[2][4];
#pragma unroll
                for (int i16 = 0; i16 < 2; ++i16) {
                    int m0 = warpM * 32 + i16 * 16;
                    const float* base = &sa[(m0 + g) * AS + kb + t];
                    af[i16][0] = f2tf(base[0]);
                    af[i16][1] = f2tf(base[8 * AS]);
                    af[i16][2] = f2tf(base[4]);
                    af[i16][3] = f2tf(base[8 * AS + 4]);
                }
#pragma unroll
                for (int j = 0; j < NJ1; ++j) {
                    int n0 = warpN * (HO1 / 2) + j * 8;
                    unsigned b0 = f2tf(sb[(kb + t) * BS + n0 + g]);
                    unsigned b1 = f2tf(sb[(kb + t + 4) * BS + n0 + g]);
#pragma unroll
                    for (int i16 = 0; i16 < 2; ++i16)
                        mma_tf32(acc[i16][j][0], acc[i16][j][1],
                                 acc[i16][j][2], acc[i16][j][3],
                                 af[i16][0], af[i16][1], af[i16][2], af[i16][3],
                                 b0, b1);
                }
            }
            __syncthreads();
        }

        // epilogue: bias + relu, tf32 into shH
#pragma unroll
        for (int i16 = 0; i16 < 2; ++i16) {
            int rA = warpM * 32 + i16 * 16 + g;
            int rB = rA + 8;
#pragma unroll
            for (int j = 0; j < NJ1; ++j) {
                int col = warpN * (HO1 / 2) + j * 8 + 2 * t;
                float2 bv = *reinterpret_cast<const float2*>(&b1v[col]);
                shH[rA * HS + col]     = f2tf(fmaxf(acc[i16][j][0] + bv.x, 0.f));
                shH[rA * HS + col + 1] = f2tf(fmaxf(acc[i16][j][1] + bv.y, 0.f));
                shH[rB * HS + col]     = f2tf(fmaxf(acc[i16][j][2] + bv.x, 0.f));
                shH[rB * HS + col + 1] = f2tf(fmaxf(acc[i16][j][3] + bv.y, 0.f));
            }
        }
        __syncthreads();
    }

    // ---- phase 2 stage loader: W3 only ----
    auto load2 = [&](int buf, int s) {
        const int kt = s * KT;
        unsigned bb = shB_s + (unsigned)(buf * BBUF) * 4u;
#pragma unroll
        for (int i = tid; i < KT * (HO2 / 4); i += 256) {
            int row = i / (HO2 / 4), c4 = i % (HO2 / 4);
            cp16(bb + (unsigned)(row * BS2 + c4 * 4) * 4u,
                 &W3[(kt + row) * HO2 + c4 * 4], 16);
        }
    };

    // ============================ PHASE 2 ============================
    {
        float acc[2][NJ2][4];
#pragma unroll
        for (int i = 0; i < 2; ++i)
#pragma unroll
            for (int j = 0; j < NJ2; ++j)
#pragma unroll
                for (int c = 0; c < 4; ++c) acc[i][j][c] = 0.0f;

        load2(0, 0); CP_COMMIT();

        for (int s = 0; s < NST2; ++s) {
            const int buf = s & 1;
            if (s + 1 < NST2) { load2(buf ^ 1, s + 1); CP_COMMIT(); CP_WAIT1(); }
            else              { CP_WAIT0(); }
            __syncthreads();

            const int kt = s * KT;
            const float* sb = shB + buf * BBUF;
#pragma unroll
            for (int k8 = 0; k8 < KT / 8; ++k8) {
                const int kb = k8 * 8;
                unsigned af[2][4];
#pragma unroll
                for (int i16 = 0; i16 < 2; ++i16) {
                    int m0 = warpM * 32 + i16 * 16;
                    const unsigned* base = &shH[(m0 + g) * HS + kt + kb + t];
                    af[i16][0] = base[0];
                    af[i16][1] = base[8 * HS];
                    af[i16][2] = base[4];
                    af[i16][3] = base[8 * HS + 4];
                }
#pragma unroll
                for (int j = 0; j < NJ2; ++j) {
                    int n0 = warpN * (HO2 / 2) + j * 8;
                    unsigned b0 = f2tf(sb[(kb + t) * BS2 + n0 + g]);
                    unsigned b1 = f2tf(sb[(kb + t + 4) * BS2 + n0 + g]);
#pragma unroll
                    for (int i16 = 0; i16 < 2; ++i16)
                        mma_tf32(acc[i16][j][0], acc[i16][j][1],
                                 acc[i16][j][2], acc[i16][j][3],
                                 af[i16][0], af[i16][1], af[i16][2], af[i16][3],
                                 b0, b1);
                }
            }
            __syncthreads();
        }

        // epilogue: bias (+relu) to global
#pragma unroll
        for (int i16 = 0; i16 < 2; ++i16) {
            int rA = row0 + warpM * 32 + i16 * 16 + g;
            int rB = rA + 8;
#pragma unroll
            for (int j = 0; j < NJ2; ++j) {
                int col = warpN * (HO2 / 2) + j * 8 + 2 * t;
                float2 bv = *reinterpret_cast<const float2*>(&b3v[col]);
                if (rA < n) {
                    float2 o;
                    o.x = acc[i16][j][0] + bv.x;
                    o.y = acc[i16][j][1] + bv.y;
                    if (RELU2) { o.x = fmaxf(o.x, 0.f); o.y = fmaxf(o.y, 0.f); }
                    *reinterpret_cast<float2*>(&C[rA * HO2 + col]) = o;
                }
                if (rB < n) {
                    float2 o;
                    o.x = acc[i16][j][2] + bv.x;
                    o.y = acc[i16][j][3] + bv.y;
                    if (RELU2) { o.x = fmaxf(o.x, 0.f); o.y = fmaxf(o.y, 0.f); }
                    *reinterpret_cast<float2*>(&C[rB * HO2 + col]) = o;
                }
            }
        }
    }
}

// Fused wrappers.
__global__ void __launch_bounds__(256, 2)
kfusedA(const float* __restrict__ xin,
        const float* __restrict__ W1l, const float* __restrict__ W1r,
        const float* __restrict__ b1,
        const float* __restrict__ Wlin1, const float* __restrict__ blin1,
        int n) {
    fused_body<64, 64, 128, true>(s_agA, xin, W1l, W1r, b1, Wlin1, blin1, s_t2, n);
}
__global__ void __launch_bounds__(256, 2)
kfusedB(const float* __restrict__ W2l, const float* __restrict__ W2r,
        const float* __restrict__ b2,
        const float* __restrict__ Wlin2, const float* __restrict__ blin2,
        float* __restrict__ outp, int n) {
    fused_body<128, 128, 64, false>(s_agB, s_t2, W2l, W2r, b2, Wlin2, blin2, outp, n);
}

// ---------------------------------------------------------------------------
// Launch. Inputs (metadata order): x, edge_index, W1l, b1, W1r, Wlin1, blin1,
//                                  W2l, b2, W2r, Wlin2, blin2
// ---------------------------------------------------------------------------
extern "C" void kernel_launch(void* const* d_in, const int* in_sizes, int n_in,
                              void* d_out, int out_size) {
    const float* xin   = (const float*)d_in[0];
    const int*   eidx  = (const int*)d_in[1];
    const float* W1l   = (const float*)d_in[2];
    const float* b1    = (const float*)d_in[3];
    const float* W1r   = (const float*)d_in[4];
    const float* Wlin1 = (const float*)d_in[5];
    const float* blin1 = (const float*)d_in[6];
    const float* W2l   = (const float*)d_in[7];
    const float* b2    = (const float*)d_in[8];
    const float* W2r   = (const float*)d_in[9];
    const float* Wlin2 = (const float*)d_in[10];
    const float* blin2 = (const float*)d_in[11];
    float*       outp  = (float*)d_out;

    const int n = in_sizes[0] / P_D;   // 100000
    const int E = in_sizes[1] / 2;     // 1600000

    // Dynamic smem: (128*132 + 2*128*20 + 2*16*136) * 4 = 105472 bytes
    const int SMEM_BYTES = (128 * 132 + 2 * 128 * 20 + 2 * 16 * 136) * 4;
    cudaFuncSetAttribute(kfusedA, cudaFuncAttributeMaxDynamicSharedMemorySize, SMEM_BYTES);
    cudaFuncSetAttribute(kfusedB, cudaFuncAttributeMaxDynamicSharedMemorySize, SMEM_BYTES);

    // --- CSR build (once; shared by both layers) ---
    kcsr_zero<<<(P_N + 256) / 256, 256>>>();
    kcsr_hist<<<(E + 255) / 256, 256>>>(eidx, E);
    kcsr_scan<<<1, 1024>>>();
    kcsr_fill<<<(E + 255) / 256, 256>>>(eidx, E);

    const int nblk  = (n + 127) / 128;
    const int nblkG = (n + 7) / 8;

    // Layer block 1: gather + fused (sage1 + lin1)
    kg_one<<<nblkG, 256>>>(reinterpret_cast<const float2*>(xin));
    kfusedA<<<nblk, 256, SMEM_BYTES>>>(xin, W1l, W1r, b1, Wlin1, blin1, n);

    // Layer block 2: gather + fused (sage2 + lin2)
    kg_two<<<nblkG, 256>>>(0);
    kfusedB<<<nblk, 256, SMEM_BYTES>>>(W2l, W2r, b2, Wlin2, blin2, outp, n);
}

// round 16
// speedup vs baseline: 2.9384x; 1.0092x over previous
#include <cuda_runtime.h>
#include <cstdint>

// Problem constants (fixed by the dataset)
#define P_N 100000
#define P_E 1600000
#define P_D 64
#define P_H 128
#define P_O 64

// Scratch: __device__ globals, only ever touched from device code.
__device__ float s_agA[P_N * P_D];     // layer-1 neighbor means  (25.6 MB)
__device__ float s_t2 [P_N * P_H];     // h2                      (51.2 MB)
__device__ float s_agB[P_N * P_H];     // layer-2 neighbor means  (51.2 MB)
// CSR scratch
__device__ int   g_ecnt  [P_N + 1];
__device__ int   g_rowptr[P_N + 1];
__device__ int   g_cursor[P_N + 1];
__device__ int   g_srcs  [P_E];
// Pre-converted tf32 weights (bits)
__device__ unsigned w1l_tf[P_D * P_H];     // 8192
__device__ unsigned w1r_tf[P_D * P_H];     // 8192
__device__ unsigned wl1_tf[P_H * P_H];     // 16384
__device__ unsigned w2l_tf[P_H * P_H];     // 16384
__device__ unsigned w2r_tf[P_H * P_H];     // 16384
__device__ unsigned wl2_tf[P_H * P_O];     // 8192

// ---------------------------------------------------------------------------
// tf32 / cp.async helpers
// ---------------------------------------------------------------------------
__device__ __forceinline__ unsigned f2tf(float f) {
    unsigned u;
    asm("cvt.rna.tf32.f32 %0, %1;" : "=r"(u) : "f"(f));
    return u;
}
__device__ __forceinline__ void mma_tf32(float& d0, float& d1, float& d2, float& d3,
                                         unsigned a0, unsigned a1, unsigned a2, unsigned a3,
                                         unsigned b0, unsigned b1) {
    asm volatile(
        "mma.sync.aligned.m16n8k8.row.col.f32.tf32.tf32.f32 "
        "{%0,%1,%2,%3}, {%4,%5,%6,%7}, {%8,%9}, {%0,%1,%2,%3};"
        : "+f"(d0), "+f"(d1), "+f"(d2), "+f"(d3)
        : "r"(a0), "r"(a1), "r"(a2), "r"(a3), "r"(b0), "r"(b1));
}
__device__ __forceinline__ void cp16(unsigned saddr, const void* g, int bytes) {
    asm volatile("cp.async.cg.shared.global [%0], [%1], 16, %2;"
                 :: "r"(saddr), "l"(g), "r"(bytes) : "memory");
}
#define CP_COMMIT() asm volatile("cp.async.commit_group;" ::: "memory")
#define CP_WAIT1()  asm volatile("cp.async.wait_group 1;" ::: "memory")
#define CP_WAIT0()  asm volatile("cp.async.wait_group 0;" ::: "memory")

// ---------------------------------------------------------------------------
// Weight pre-conversion: fp32 -> tf32 bits, once per launch.
// ---------------------------------------------------------------------------
__global__ void kconv_w(const float* __restrict__ W1l, const float* __restrict__ W1r,
                        const float* __restrict__ Wlin1, const float* __restrict__ W2l,
                        const float* __restrict__ W2r, const float* __restrict__ Wlin2) {
    int idx = blockIdx.x * blockDim.x + threadIdx.x;
    int stride = gridDim.x * blockDim.x;
    for (int i = idx; i < P_D * P_H; i += stride) w1l_tf[i] = f2tf(W1l[i]);
    for (int i = idx; i < P_D * P_H; i += stride) w1r_tf[i] = f2tf(W1r[i]);
    for (int i = idx; i < P_H * P_H; i += stride) wl1_tf[i] = f2tf(Wlin1[i]);
    for (int i = idx; i < P_H * P_H; i += stride) w2l_tf[i] = f2tf(W2l[i]);
    for (int i = idx; i < P_H * P_H; i += stride) w2r_tf[i] = f2tf(W2r[i]);
    for (int i = idx; i < P_H * P_O; i += stride) wl2_tf[i] = f2tf(Wlin2[i]);
}

// ---------------------------------------------------------------------------
// CSR build
// ---------------------------------------------------------------------------
__global__ void kcsr_zero() {
    int i = blockIdx.x * blockDim.x + threadIdx.x;
    if (i <= P_N) g_ecnt[i] = 0;
}
__global__ void kcsr_hist(const int* __restrict__ ei, int E) {
    int e = blockIdx.x * blockDim.x + threadIdx.x;
    if (e >= E) return;
    atomicAdd(&g_ecnt[ei[E + e]], 1);
}
__global__ void kcsr_scan() {
    __shared__ int part[1024];
    const int tid   = threadIdx.x;
    const int chunk = (P_N + 1023) / 1024;
    int lo = tid * chunk;
    int hi = lo + chunk; if (hi > P_N) hi = P_N;
    if (lo > P_N) lo = P_N;
    int s = 0;
    for (int i = lo; i < hi; ++i) s += g_ecnt[i];
    part[tid] = s;
    __syncthreads();
    for (int off = 1; off < 1024; off <<= 1) {
        int v = 0;
        if (tid >= off) v = part[tid - off];
        __syncthreads();
        if (tid >= off) part[tid] += v;
        __syncthreads();
    }
    int run = part[tid] - s;
    for (int i = lo; i < hi; ++i) {
        g_rowptr[i] = run;
        g_cursor[i] = run;
        run += g_ecnt[i];
    }
    if (hi == P_N) g_rowptr[P_N] = run;
}
__global__ void kcsr_fill(const int* __restrict__ ei, int E) {
    int e = blockIdx.x * blockDim.x + threadIdx.x;
    if (e >= E) return;
    int dst = ei[E + e];
    int pos = atomicAdd(&g_cursor[dst], 1);
    g_srcs[pos] = ei[e];
}

// ---------------------------------------------------------------------------
// Gather layer 1: s_agA[i] = mean over CSR row i of x[src]  (D=64).
// ---------------------------------------------------------------------------
__global__ void kg_one(const float2* __restrict__ x2) {
    int w    = (blockIdx.x * blockDim.x + threadIdx.x) >> 5;
    int lane = threadIdx.x & 31;
    if (w >= P_N) return;
    int lo = g_rowptr[w], hi = g_rowptr[w + 1];
    float ax0 = 0.f, ay0 = 0.f, ax1 = 0.f, ay1 = 0.f;
    int e = lo;
    for (; e + 1 < hi; e += 2) {
        int s0 = g_srcs[e], s1 = g_srcs[e + 1];
        float2 v0 = x2[s0 * 32 + lane];
        float2 v1 = x2[s1 * 32 + lane];
        ax0 += v0.x; ay0 += v0.y;
        ax1 += v1.x; ay1 += v1.y;
    }
    if (e < hi) {
        float2 v = x2[g_srcs[e] * 32 + lane];
        ax0 += v.x; ay0 += v.y;
    }
    int deg = hi - lo;
    float inv = (deg > 0) ? (1.0f / (float)deg) : 1.0f;
    float2 o;
    o.x = (ax0 + ax1) * inv;
    o.y = (ay0 + ay1) * inv;
    reinterpret_cast<float2*>(s_agA)[w * 32 + lane] = o;
}

// ---------------------------------------------------------------------------
// Gather layer 2: s_agB[i] = mean over CSR row i of s_t2[src]  (H=128).
// ---------------------------------------------------------------------------
__global__ void kg_two(int dummy) {
    int w    = (blockIdx.x * blockDim.x + threadIdx.x) >> 5;
    int lane = threadIdx.x & 31;
    if (w >= P_N) return;
    int lo = g_rowptr[w], hi = g_rowptr[w + 1];
    const float4* h4 = reinterpret_cast<const float4*>(s_t2);
    float a0[4] = {0.f, 0.f, 0.f, 0.f};
    float a1[4] = {0.f, 0.f, 0.f, 0.f};
    int e = lo;
    for (; e + 1 < hi; e += 2) {
        int s0 = g_srcs[e], s1 = g_srcs[e + 1];
        float4 v0 = h4[s0 * 32 + lane];
        float4 v1 = h4[s1 * 32 + lane];
        a0[0] += v0.x; a0[1] += v0.y; a0[2] += v0.z; a0[3] += v0.w;
        a1[0] += v1.x; a1[1] += v1.y; a1[2] += v1.z; a1[3] += v1.w;
    }
    if (e < hi) {
        float4 v = h4[g_srcs[e] * 32 + lane];
        a0[0] += v.x; a0[1] += v.y; a0[2] += v.z; a0[3] += v.w;
    }
    int deg = hi - lo;
    float inv = (deg > 0) ? (1.0f / (float)deg) : 1.0f;
    float4 o;
    o.x = (a0[0] + a1[0]) * inv;
    o.y = (a0[1] + a1[1]) * inv;
    o.z = (a0[2] + a1[2]) * inv;
    o.w = (a0[3] + a1[3]) * inv;
    reinterpret_cast<float4*>(s_agB)[w * 32 + lane] = o;
}

// ---------------------------------------------------------------------------
// Fused two-stage TF32 GEMM, cp.async double-buffered, PRE-CONVERTED W.
//   phase1: H = relu( A1 @ W1 [+ A2 @ W2] + b1 )   (HO1=128, tf32 h-tile in smem)
//   phase2: C = act ( H @ W3 + b3 )                 (HO2 = 128 or 64)
// W1/W2/W3 hold tf32 bits -> B fragment loads are plain LDS (no cvt).
// A staged raw fp32 (zfill OOB), cvt at fragment load (idempotent on tf32).
// ---------------------------------------------------------------------------
template<int K1, int K2, int HO2, bool RELU2>
__device__ __forceinline__ void fused_body(const float* A1, const float* A2,
                                           const unsigned* W1, const unsigned* W2,
                                           const float* b1v,
                                           const unsigned* W3, const float* b3v,
                                           float* C, int n) {
    constexpr int MT   = 128;
    constexpr int KT   = 16;
    constexpr int KTOT = K1 + K2;
    constexpr int NST1 = KTOT / KT;
    constexpr int NST2 = 128 / KT;
    constexpr int HO1  = 128;
    constexpr int AS   = KT + 4;        // 20
    constexpr int BS   = HO1 + 8;       // 136
    constexpr int HS   = HO1 + 4;       // 132
    constexpr int BS2  = HO2 + 8;
    constexpr int NJ1  = 8;
    constexpr int NJ2  = (HO2 / 2) / 8;
    constexpr int ABUF = MT * AS;       // 2560 words
    constexpr int BBUF = KT * BS;       // 2176 words

    extern __shared__ __align__(16) float dsm[];
    unsigned* shH = reinterpret_cast<unsigned*>(dsm);       // 16896 words
    float*    shA = dsm + MT * HS;                          // 2 x 2560
    unsigned* shB = reinterpret_cast<unsigned*>(dsm + MT * HS + 2 * ABUF); // 2 x 2176

    const unsigned shA_s = (unsigned)__cvta_generic_to_shared(shA);
    const unsigned shB_s = (unsigned)__cvta_generic_to_shared(shB);

    const int tid   = threadIdx.x;
    const int lane  = tid & 31;
    const int warp  = tid >> 5;
    const int warpM = warp & 3;
    const int warpN = warp >> 2;
    const int g     = lane >> 2;
    const int t     = lane & 3;
    const int row0  = blockIdx.x * MT;

    // ---- phase 1 stage loader ----
    auto load1 = [&](int buf, int s) {
        const int kt = s * KT;
        const unsigned* Wsrc; int wkb;
        if (kt < K1) { Wsrc = W1; wkb = kt; } else { Wsrc = W2; wkb = kt - K1; }
        unsigned bb = shB_s + (unsigned)(buf * BBUF) * 4u;
#pragma unroll
        for (int i = tid; i < KT * (HO1 / 4); i += 256) {
            int row = i >> 5, c4 = i & 31;
            cp16(bb + (unsigned)(row * BS + c4 * 4) * 4u,
                 &Wsrc[(wkb + row) * HO1 + c4 * 4], 16);
        }
        const float* Asrc; int kbase, KA;
        if (kt < K1) { Asrc = A1; kbase = kt;      KA = K1; }
        else         { Asrc = A2; kbase = kt - K1; KA = (K2 > 0) ? K2 : 1; }
        unsigned ab = shA_s + (unsigned)(buf * ABUF) * 4u;
#pragma unroll
        for (int i = tid; i < MT * (KT / 4); i += 256) {
            int r = i >> 2, lk4 = i & 3;
            int gr = row0 + r;
            int ok = (gr < n);
            int grc = ok ? gr : 0;
            cp16(ab + (unsigned)(r * AS + lk4 * 4) * 4u,
                 &Asrc[(size_t)grc * KA + kbase + lk4 * 4], ok ? 16 : 0);
        }
    };

    // ============================ PHASE 1 ============================
    {
        float acc[2][NJ1][4];
#pragma unroll
        for (int i = 0; i < 2; ++i)
#pragma unroll
            for (int j = 0; j < NJ1; ++j)
#pragma unroll
                for (int c = 0; c < 4; ++c) acc[i][j][c] = 0.0f;

        load1(0, 0); CP_COMMIT();

        for (int s = 0; s < NST1; ++s) {
            const int buf = s & 1;
            if (s + 1 < NST1) { load1(buf ^ 1, s + 1); CP_COMMIT(); CP_WAIT1(); }
            else              { CP_WAIT0(); }
            __syncthreads();

            const float*    sa = shA + buf * ABUF;
            const unsigned* sb = shB + buf * BBUF;
#pragma unroll
            for (int k8 = 0; k8 < KT / 8; ++k8) {
                const int kb = k8 * 8;
                unsigned af[2][4];
#pragma unroll
                for (int i16 = 0; i16 < 2; ++i16) {
                    int m0 = warpM * 32 + i16 * 16;
                    const float* base = &sa[(m0 + g) * AS + kb + t];
                    af[i16][0] = f2tf(base[0]);
                    af[i16][1] = f2tf(base[8 * AS]);
                    af[i16][2] = f2tf(base[4]);
                    af[i16][3] = f2tf(base[8 * AS + 4]);
                }
#pragma unroll
                for (int j = 0; j < NJ1; ++j) {
                    int n0 = warpN * (HO1 / 2) + j * 8;
                    unsigned b0 = sb[(kb + t) * BS + n0 + g];
                    unsigned b1 = sb[(kb + t + 4) * BS + n0 + g];
#pragma unroll
                    for (int i16 = 0; i16 < 2; ++i16)
                        mma_tf32(acc[i16][j][0], acc[i16][j][1],
                                 acc[i16][j][2], acc[i16][j][3],
                                 af[i16][0], af[i16][1], af[i16][2], af[i16][3],
                                 b0, b1);
                }
            }
            __syncthreads();
        }

        // epilogue: bias + relu, tf32 into shH
#pragma unroll
        for (int i16 = 0; i16 < 2; ++i16) {
            int rA = warpM * 32 + i16 * 16 + g;
            int rB = rA + 8;
#pragma unroll
            for (int j = 0; j < NJ1; ++j) {
                int col = warpN * (HO1 / 2) + j * 8 + 2 * t;
                float2 bv = *reinterpret_cast<const float2*>(&b1v[col]);
                shH[rA * HS + col]     = f2tf(fmaxf(acc[i16][j][0] + bv.x, 0.f));
                shH[rA * HS + col + 1] = f2tf(fmaxf(acc[i16][j][1] + bv.y, 0.f));
                shH[rB * HS + col]     = f2tf(fmaxf(acc[i16][j][2] + bv.x, 0.f));
                shH[rB * HS + col + 1] = f2tf(fmaxf(acc[i16][j][3] + bv.y, 0.f));
            }
        }
        __syncthreads();
    }

    // ---- phase 2 stage loader: W3 only (tf32 bits) ----
    auto load2 = [&](int buf, int s) {
        const int kt = s * KT;
        unsigned bb = shB_s + (unsigned)(buf * BBUF) * 4u;
#pragma unroll
        for (int i = tid; i < KT * (HO2 / 4); i += 256) {
            int row = i / (HO2 / 4), c4 = i % (HO2 / 4);
            cp16(bb + (unsigned)(row * BS2 + c4 * 4) * 4u,
                 &W3[(kt + row) * HO2 + c4 * 4], 16);
        }
    };

    // ============================ PHASE 2 ============================
    {
        float acc[2][NJ2][4];
#pragma unroll
        for (int i = 0; i < 2; ++i)
#pragma unroll
            for (int j = 0; j < NJ2; ++j)
#pragma unroll
                for (int c = 0; c < 4; ++c) acc[i][j][c] = 0.0f;

        load2(0, 0); CP_COMMIT();

        for (int s = 0; s < NST2; ++s) {
            const int buf = s & 1;
            if (s + 1 < NST2) { load2(buf ^ 1, s + 1); CP_COMMIT(); CP_WAIT1(); }
            else              { CP_WAIT0(); }
            __syncthreads();

            const int kt = s * KT;
            const unsigned* sb = shB + buf * BBUF;
#pragma unroll
            for (int k8 = 0; k8 < KT / 8; ++k8) {
                const int kb = k8 * 8;
                unsigned af[2][4];
#pragma unroll
                for (int i16 = 0; i16 < 2; ++i16) {
                    int m0 = warpM * 32 + i16 * 16;
                    const unsigned* base = &shH[(m0 + g) * HS + kt + kb + t];
                    af[i16][0] = base[0];
                    af[i16][1] = base[8 * HS];
                    af[i16][2] = base[4];
                    af[i16][3] = base[8 * HS + 4];
                }
#pragma unroll
                for (int j = 0; j < NJ2; ++j) {
                    int n0 = warpN * (HO2 / 2) + j * 8;
                    unsigned b0 = sb[(kb + t) * BS2 + n0 + g];
                    unsigned b1 = sb[(kb + t + 4) * BS2 + n0 + g];
#pragma unroll
                    for (int i16 = 0; i16 < 2; ++i16)
                        mma_tf32(acc[i16][j][0], acc[i16][j][1],
                                 acc[i16][j][2], acc[i16][j][3],
                                 af[i16][0], af[i16][1], af[i16][2], af[i16][3],
                                 b0, b1);
                }
            }
            __syncthreads();
        }

        // epilogue: bias (+relu) to global
#pragma unroll
        for (int i16 = 0; i16 < 2; ++i16) {
            int rA = row0 + warpM * 32 + i16 * 16 + g;
            int rB = rA + 8;
#pragma unroll
            for (int j = 0; j < NJ2; ++j) {
                int col = warpN * (HO2 / 2) + j * 8 + 2 * t;
                float2 bv = *reinterpret_cast<const float2*>(&b3v[col]);
                if (rA < n) {
                    float2 o;
                    o.x = acc[i16][j][0] + bv.x;
                    o.y = acc[i16][j][1] + bv.y;
                    if (RELU2) { o.x = fmaxf(o.x, 0.f); o.y = fmaxf(o.y, 0.f); }
                    *reinterpret_cast<float2*>(&C[rA * HO2 + col]) = o;
                }
                if (rB < n) {
                    float2 o;
                    o.x = acc[i16][j][2] + bv.x;
                    o.y = acc[i16][j][3] + bv.y;
                    if (RELU2) { o.x = fmaxf(o.x, 0.f); o.y = fmaxf(o.y, 0.f); }
                    *reinterpret_cast<float2*>(&C[rB * HO2 + col]) = o;
                }
            }
        }
    }
}

// Fused wrappers (tf32 weights from __device__ buffers).
__global__ void __launch_bounds__(256, 2)
kfusedA(const float* __restrict__ xin,
        const float* __restrict__ b1, const float* __restrict__ blin1, int n) {
    fused_body<64, 64, 128, true>(s_agA, xin, w1l_tf, w1r_tf, b1, wl1_tf, blin1, s_t2, n);
}
__global__ void __launch_bounds__(256, 2)
kfusedB(const float* __restrict__ b2, const float* __restrict__ blin2,
        float* __restrict__ outp, int n) {
    fused_body<128, 128, 64, false>(s_agB, s_t2, w2l_tf, w2r_tf, b2, wl2_tf, blin2, outp, n);
}

// ---------------------------------------------------------------------------
// Launch. Inputs (metadata order): x, edge_index, W1l, b1, W1r, Wlin1, blin1,
//                                  W2l, b2, W2r, Wlin2, blin2
// ---------------------------------------------------------------------------
extern "C" void kernel_launch(void* const* d_in, const int* in_sizes, int n_in,
                              void* d_out, int out_size) {
    const float* xin   = (const float*)d_in[0];
    const int*   eidx  = (const int*)d_in[1];
    const float* W1l   = (const float*)d_in[2];
    const float* b1    = (const float*)d_in[3];
    const float* W1r   = (const float*)d_in[4];
    const float* Wlin1 = (const float*)d_in[5];
    const float* blin1 = (const float*)d_in[6];
    const float* W2l   = (const float*)d_in[7];
    const float* b2    = (const float*)d_in[8];
    const float* W2r   = (const float*)d_in[9];
    const float* Wlin2 = (const float*)d_in[10];
    const float* blin2 = (const float*)d_in[11];
    float*       outp  = (float*)d_out;

    const int n = in_sizes[0] / P_D;   // 100000
    const int E = in_sizes[1] / 2;     // 1600000

    // Dynamic smem: (128*132 + 2*128*20 + 2*16*136) * 4 = 105472 bytes
    const int SMEM_BYTES = (128 * 132 + 2 * 128 * 20 + 2 * 16 * 136) * 4;
    cudaFuncSetAttribute(kfusedA, cudaFuncAttributeMaxDynamicSharedMemorySize, SMEM_BYTES);
    cudaFuncSetAttribute(kfusedB, cudaFuncAttributeMaxDynamicSharedMemorySize, SMEM_BYTES);

    // Weight pre-conversion (tiny) + CSR build
    kconv_w<<<64, 256>>>(W1l, W1r, Wlin1, W2l, W2r, Wlin2);
    kcsr_zero<<<(P_N + 256) / 256, 256>>>();
    kcsr_hist<<<(E + 255) / 256, 256>>>(eidx, E);
    kcsr_scan<<<1, 1024>>>();
    kcsr_fill<<<(E + 255) / 256, 256>>>(eidx, E);

    const int nblk  = (n + 127) / 128;
    const int nblkG = (n + 7) / 8;

    // Layer block 1: gather + fused (sage1 + lin1)
    kg_one<<<nblkG, 256>>>(reinterpret_cast<const float2*>(xin));
    kfusedA<<<nblk, 256, SMEM_BYTES>>>(xin, b1, blin1, n);

    // Layer block 2: gather + fused (sage2 + lin2)
    kg_two<<<nblkG, 256>>>(0);
    kfusedB<<<nblk, 256, SMEM_BYTES>>>(b2, blin2, outp, n);
}

// round 17
// speedup vs baseline: 4.6241x; 1.5737x over previous
#include <cuda_runtime.h>
#include <cstdint>

// Problem constants (fixed by the dataset)
#define P_N 100000
#define P_E 1600000
#define P_D 64
#define P_H 128
#define P_O 64

#define SCAN_BLK 1024
#define SCAN_NB  ((P_N + SCAN_BLK - 1) / SCAN_BLK)   // 98

// Scratch: __device__ globals, only ever touched from device code.
__device__ float s_agA[P_N * P_D];     // layer-1 neighbor means  (25.6 MB)
__device__ float s_t2 [P_N * P_H];     // h2                      (51.2 MB)
__device__ float s_agB[P_N * P_H];     // layer-2 neighbor means  (51.2 MB)
// CSR scratch
__device__ int   g_ecnt  [P_N + 1];
__device__ int   g_rowptr[P_N + 1];
__device__ int   g_cursor[P_N + 1];
__device__ int   g_srcs  [P_E];
__device__ int   g_part  [SCAN_NB * SCAN_BLK];
__device__ int   g_bsum  [SCAN_NB];
__device__ int   g_boff  [SCAN_NB];
// Pre-converted tf32 weights (bits)
__device__ unsigned w1l_tf[P_D * P_H];
__device__ unsigned w1r_tf[P_D * P_H];
__device__ unsigned wl1_tf[P_H * P_H];
__device__ unsigned w2l_tf[P_H * P_H];
__device__ unsigned w2r_tf[P_H * P_H];
__device__ unsigned wl2_tf[P_H * P_O];

// ---------------------------------------------------------------------------
// tf32 / cp.async helpers
// ---------------------------------------------------------------------------
__device__ __forceinline__ unsigned f2tf(float f) {
    unsigned u;
    asm("cvt.rna.tf32.f32 %0, %1;" : "=r"(u) : "f"(f));
    return u;
}
__device__ __forceinline__ void mma_tf32(float& d0, float& d1, float& d2, float& d3,
                                         unsigned a0, unsigned a1, unsigned a2, unsigned a3,
                                         unsigned b0, unsigned b1) {
    asm volatile(
        "mma.sync.aligned.m16n8k8.row.col.f32.tf32.tf32.f32 "
        "{%0,%1,%2,%3}, {%4,%5,%6,%7}, {%8,%9}, {%0,%1,%2,%3};"
        : "+f"(d0), "+f"(d1), "+f"(d2), "+f"(d3)
        : "r"(a0), "r"(a1), "r"(a2), "r"(a3), "r"(b0), "r"(b1));
}
__device__ __forceinline__ void cp16(unsigned saddr, const void* g, int bytes) {
    asm volatile("cp.async.cg.shared.global [%0], [%1], 16, %2;"
                 :: "r"(saddr), "l"(g), "r"(bytes) : "memory");
}
#define CP_COMMIT() asm volatile("cp.async.commit_group;" ::: "memory")
#define CP_WAIT1()  asm volatile("cp.async.wait_group 1;" ::: "memory")
#define CP_WAIT0()  asm volatile("cp.async.wait_group 0;" ::: "memory")

// ---------------------------------------------------------------------------
// Weight pre-conversion
// ---------------------------------------------------------------------------
__global__ void kconv_w(const float* __restrict__ W1l, const float* __restrict__ W1r,
                        const float* __restrict__ Wlin1, const float* __restrict__ W2l,
                        const float* __restrict__ W2r, const float* __restrict__ Wlin2) {
    int idx = blockIdx.x * blockDim.x + threadIdx.x;
    int stride = gridDim.x * blockDim.x;
    for (int i = idx; i < P_D * P_H; i += stride) w1l_tf[i] = f2tf(W1l[i]);
    for (int i = idx; i < P_D * P_H; i += stride) w1r_tf[i] = f2tf(W1r[i]);
    for (int i = idx; i < P_H * P_H; i += stride) wl1_tf[i] = f2tf(Wlin1[i]);
    for (int i = idx; i < P_H * P_H; i += stride) w2l_tf[i] = f2tf(W2l[i]);
    for (int i = idx; i < P_H * P_H; i += stride) w2r_tf[i] = f2tf(W2r[i]);
    for (int i = idx; i < P_H * P_O; i += stride) wl2_tf[i] = f2tf(Wlin2[i]);
}

// ---------------------------------------------------------------------------
// CSR build: zero + hist + PARALLEL 2-level scan + fill
// ---------------------------------------------------------------------------
__global__ void kcsr_zero() {
    int i = blockIdx.x * blockDim.x + threadIdx.x;
    if (i <= P_N) g_ecnt[i] = 0;
}
__global__ void kcsr_hist(const int* __restrict__ ei, int E) {
    int e = blockIdx.x * blockDim.x + threadIdx.x;
    if (e >= E) return;
    atomicAdd(&g_ecnt[ei[E + e]], 1);
}
// scan level 1: per-block exclusive scan of 1024 counts + block sum
__global__ void kscan1() {
    __shared__ int sm[SCAN_BLK];
    int tid = threadIdx.x;
    int gid = blockIdx.x * SCAN_BLK + tid;
    int v = (gid < P_N) ? g_ecnt[gid] : 0;
    sm[tid] = v;
    __syncthreads();
#pragma unroll
    for (int off = 1; off < SCAN_BLK; off <<= 1) {
        int t = 0;
        if (tid >= off) t = sm[tid - off];
        __syncthreads();
        if (tid >= off) sm[tid] += t;
        __syncthreads();
    }
    g_part[gid] = sm[tid] - v;                 // exclusive within block
    if (tid == SCAN_BLK - 1) g_bsum[blockIdx.x] = sm[tid];
}
// scan level 2: exclusive scan of the 98 block sums (one tiny block)
__global__ void kscan2() {
    __shared__ int sm[128];
    int tid = threadIdx.x;                     // 128 threads
    int v = (tid < SCAN_NB) ? g_bsum[tid] : 0;
    sm[tid] = v;
    __syncthreads();
#pragma unroll
    for (int off = 1; off < 128; off <<= 1) {
        int t = 0;
        if (tid >= off) t = sm[tid - off];
        __syncthreads();
        if (tid >= off) sm[tid] += t;
        __syncthreads();
    }
    if (tid < SCAN_NB) g_boff[tid] = sm[tid] - v;
}
// scan level 3: combine, write rowptr + cursor
__global__ void kscan3(int E) {
    int gid = blockIdx.x * SCAN_BLK + threadIdx.x;
    if (gid < P_N) {
        int v = g_part[gid] + g_boff[blockIdx.x];
        g_rowptr[gid] = v;
        g_cursor[gid] = v;
    }
    if (gid == P_N) g_rowptr[P_N] = E;         // all dst in [0,N) -> total = E
}
__global__ void kcsr_fill(const int* __restrict__ ei, int E) {
    int e = blockIdx.x * blockDim.x + threadIdx.x;
    if (e >= E) return;
    int dst = ei[E + e];
    int pos = atomicAdd(&g_cursor[dst], 1);
    g_srcs[pos] = ei[e];
}

// ---------------------------------------------------------------------------
// Gather layer 1: s_agA[i] = mean over CSR row i of x[src]  (D=64).
// ---------------------------------------------------------------------------
__global__ void kg_one(const float2* __restrict__ x2) {
    int w    = (blockIdx.x * blockDim.x + threadIdx.x) >> 5;
    int lane = threadIdx.x & 31;
    if (w >= P_N) return;
    int lo = g_rowptr[w], hi = g_rowptr[w + 1];
    float ax0 = 0.f, ay0 = 0.f, ax1 = 0.f, ay1 = 0.f;
    int e = lo;
    for (; e + 1 < hi; e += 2) {
        int s0 = g_srcs[e], s1 = g_srcs[e + 1];
        float2 v0 = x2[s0 * 32 + lane];
        float2 v1 = x2[s1 * 32 + lane];
        ax0 += v0.x; ay0 += v0.y;
        ax1 += v1.x; ay1 += v1.y;
    }
    if (e < hi) {
        float2 v = x2[g_srcs[e] * 32 + lane];
        ax0 += v.x; ay0 += v.y;
    }
    int deg = hi - lo;
    float inv = (deg > 0) ? (1.0f / (float)deg) : 1.0f;
    float2 o;
    o.x = (ax0 + ax1) * inv;
    o.y = (ay0 + ay1) * inv;
    reinterpret_cast<float2*>(s_agA)[w * 32 + lane] = o;
}

// ---------------------------------------------------------------------------
// Gather layer 2: s_agB[i] = mean over CSR row i of s_t2[src]  (H=128).
// ---------------------------------------------------------------------------
__global__ void kg_two(int dummy) {
    int w    = (blockIdx.x * blockDim.x + threadIdx.x) >> 5;
    int lane = threadIdx.x & 31;
    if (w >= P_N) return;
    int lo = g_rowptr[w], hi = g_rowptr[w + 1];
    const float4* h4 = reinterpret_cast<const float4*>(s_t2);
    float a0[4] = {0.f, 0.f, 0.f, 0.f};
    float a1[4] = {0.f, 0.f, 0.f, 0.f};
    int e = lo;
    for (; e + 1 < hi; e += 2) {
        int s0 = g_srcs[e], s1 = g_srcs[e + 1];
        float4 v0 = h4[s0 * 32 + lane];
        float4 v1 = h4[s1 * 32 + lane];
        a0[0] += v0.x; a0[1] += v0.y; a0[2] += v0.z; a0[3] += v0.w;
        a1[0] += v1.x; a1[1] += v1.y; a1[2] += v1.z; a1[3] += v1.w;
    }
    if (e < hi) {
        float4 v = h4[g_srcs[e] * 32 + lane];
        a0[0] += v.x; a0[1] += v.y; a0[2] += v.z; a0[3] += v.w;
    }
    int deg = hi - lo;
    float inv = (deg > 0) ? (1.0f / (float)deg) : 1.0f;
    float4 o;
    o.x = (a0[0] + a1[0]) * inv;
    o.y = (a0[1] + a1[1]) * inv;
    o.z = (a0[2] + a1[2]) * inv;
    o.w = (a0[3] + a1[3]) * inv;
    reinterpret_cast<float4*>(s_agB)[w * 32 + lane] = o;
}

// ---------------------------------------------------------------------------
// Fused two-stage TF32 GEMM, cp.async double-buffered, pre-converted W.
// ---------------------------------------------------------------------------
template<int K1, int K2, int HO2, bool RELU2>
__device__ __forceinline__ void fused_body(const float* A1, const float* A2,
                                           const unsigned* W1, const unsigned* W2,
                                           const float* b1v,
                                           const unsigned* W3, const float* b3v,
                                           float* C, int n) {
    constexpr int MT   = 128;
    constexpr int KT   = 16;
    constexpr int KTOT = K1 + K2;
    constexpr int NST1 = KTOT / KT;
    constexpr int NST2 = 128 / KT;
    constexpr int HO1  = 128;
    constexpr int AS   = KT + 4;        // 20
    constexpr int BS   = HO1 + 8;       // 136
    constexpr int HS   = HO1 + 4;       // 132
    constexpr int BS2  = HO2 + 8;
    constexpr int NJ1  = 8;
    constexpr int NJ2  = (HO2 / 2) / 8;
    constexpr int ABUF = MT * AS;
    constexpr int BBUF = KT * BS;

    extern __shared__ __align__(16) float dsm[];
    unsigned* shH = reinterpret_cast<unsigned*>(dsm);
    float*    shA = dsm + MT * HS;
    unsigned* shB = reinterpret_cast<unsigned*>(dsm + MT * HS + 2 * ABUF);

    const unsigned shA_s = (unsigned)__cvta_generic_to_shared(shA);
    const unsigned shB_s = (unsigned)__cvta_generic_to_shared(shB);

    const int tid   = threadIdx.x;
    const int lane  = tid & 31;
    const int warp  = tid >> 5;
    const int warpM = warp & 3;
    const int warpN = warp >> 2;
    const int g     = lane >> 2;
    const int t     = lane & 3;
    const int row0  = blockIdx.x * MT;

    auto load1 = [&](int buf, int s) {
        const int kt = s * KT;
        const unsigned* Wsrc; int wkb;
        if (kt < K1) { Wsrc = W1; wkb = kt; } else { Wsrc = W2; wkb = kt - K1; }
        unsigned bb = shB_s + (unsigned)(buf * BBUF) * 4u;
#pragma unroll
        for (int i = tid; i < KT * (HO1 / 4); i += 256) {
            int row = i >> 5, c4 = i & 31;
            cp16(bb + (unsigned)(row * BS + c4 * 4) * 4u,
                 &Wsrc[(wkb + row) * HO1 + c4 * 4], 16);
        }
        const float* Asrc; int kbase, KA;
        if (kt < K1) { Asrc = A1; kbase = kt;      KA = K1; }
        else         { Asrc = A2; kbase = kt - K1; KA = (K2 > 0) ? K2 : 1; }
        unsigned ab = shA_s + (unsigned)(buf * ABUF) * 4u;
#pragma unroll
        for (int i = tid; i < MT * (KT / 4); i += 256) {
            int r = i >> 2, lk4 = i & 3;
            int gr = row0 + r;
            int ok = (gr < n);
            int grc = ok ? gr : 0;
            cp16(ab + (unsigned)(r * AS + lk4 * 4) * 4u,
                 &Asrc[(size_t)grc * KA + kbase + lk4 * 4], ok ? 16 : 0);
        }
    };

    // ============================ PHASE 1 ============================
    {
        float acc[2][NJ1][4];
#pragma unroll
        for (int i = 0; i < 2; ++i)
#pragma unroll
            for (int j = 0; j < NJ1; ++j)
#pragma unroll
                for (int c = 0; c < 4; ++c) acc[i][j][c] = 0.0f;

        load1(0, 0); CP_COMMIT();

        for (int s = 0; s < NST1; ++s) {
            const int buf = s & 1;
            if (s + 1 < NST1) { load1(buf ^ 1, s + 1); CP_COMMIT(); CP_WAIT1(); }
            else              { CP_WAIT0(); }
            __syncthreads();

            const float*    sa = shA + buf * ABUF;
            const unsigned* sb = shB + buf * BBUF;
#pragma unroll
            for (int k8 = 0; k8 < KT / 8; ++k8) {
                const int kb = k8 * 8;
                unsigned af[2][4];
#pragma unroll
                for (int i16 = 0; i16 < 2; ++i16) {
                    int m0 = warpM * 32 + i16 * 16;
                    const float* base = &sa[(m0 + g) * AS + kb + t];
                    af[i16][0] = f2tf(base[0]);
                    af[i16][1] = f2tf(base[8 * AS]);
                    af[i16][2] = f2tf(base[4]);
                    af[i16][3] = f2tf(base[8 * AS + 4]);
                }
#pragma unroll
                for (int j = 0; j < NJ1; ++j) {
                    int n0 = warpN * (HO1 / 2) + j * 8;
                    unsigned b0 = sb[(kb + t) * BS + n0 + g];
                    unsigned b1 = sb[(kb + t + 4) * BS + n0 + g];
#pragma unroll
                    for (int i16 = 0; i16 < 2; ++i16)
                        mma_tf32(acc[i16][j][0], acc[i16][j][1],
                                 acc[i16][j][2], acc[i16][j][3],
                                 af[i16][0], af[i16][1], af[i16][2], af[i16][3],
                                 b0, b1);
                }
            }
            __syncthreads();
        }

#pragma unroll
        for (int i16 = 0; i16 < 2; ++i16) {
            int rA = warpM * 32 + i16 * 16 + g;
            int rB = rA + 8;
#pragma unroll
            for (int j = 0; j < NJ1; ++j) {
                int col = warpN * (HO1 / 2) + j * 8 + 2 * t;
                float2 bv = *reinterpret_cast<const float2*>(&b1v[col]);
                shH[rA * HS + col]     = f2tf(fmaxf(acc[i16][j][0] + bv.x, 0.f));
                shH[rA * HS + col + 1] = f2tf(fmaxf(acc[i16][j][1] + bv.y, 0.f));
                shH[rB * HS + col]     = f2tf(fmaxf(acc[i16][j][2] + bv.x, 0.f));
                shH[rB * HS + col + 1] = f2tf(fmaxf(acc[i16][j][3] + bv.y, 0.f));
            }
        }
        __syncthreads();
    }

    auto load2 = [&](int buf, int s) {
        const int kt = s * KT;
        unsigned bb = shB_s + (unsigned)(buf * BBUF) * 4u;
#pragma unroll
        for (int i = tid; i < KT * (HO2 / 4); i += 256) {
            int row = i / (HO2 / 4), c4 = i % (HO2 / 4);
            cp16(bb + (unsigned)(row * BS2 + c4 * 4) * 4u,
                 &W3[(kt + row) * HO2 + c4 * 4], 16);
        }
    };

    // ============================ PHASE 2 ============================
    {
        float acc[2][NJ2][4];
#pragma unroll
        for (int i = 0; i < 2; ++i)
#pragma unroll
            for (int j = 0; j < NJ2; ++j)
#pragma unroll
                for (int c = 0; c < 4; ++c) acc[i][j][c] = 0.0f;

        load2(0, 0); CP_COMMIT();

        for (int s = 0; s < NST2; ++s) {
            const int buf = s & 1;
            if (s + 1 < NST2) { load2(buf ^ 1, s + 1); CP_COMMIT(); CP_WAIT1(); }
            else              { CP_WAIT0(); }
            __syncthreads();

            const int kt = s * KT;
            const unsigned* sb = shB + buf * BBUF;
#pragma unroll
            for (int k8 = 0; k8 < KT / 8; ++k8) {
                const int kb = k8 * 8;
                unsigned af[2][4];
#pragma unroll
                for (int i16 = 0; i16 < 2; ++i16) {
                    int m0 = warpM * 32 + i16 * 16;
                    const unsigned* base = &shH[(m0 + g) * HS + kt + kb + t];
                    af[i16][0] = base[0];
                    af[i16][1] = base[8 * HS];
                    af[i16][2] = base[4];
                    af[i16][3] = base[8 * HS + 4];
                }
#pragma unroll
                for (int j = 0; j < NJ2; ++j) {
                    int n0 = warpN * (HO2 / 2) + j * 8;
                    unsigned b0 = sb[(kb + t) * BS2 + n0 + g];
                    unsigned b1 = sb[(kb + t + 4) * BS2 + n0 + g];
#pragma unroll
                    for (int i16 = 0; i16 < 2; ++i16)
                        mma_tf32(acc[i16][j][0], acc[i16][j][1],
                                 acc[i16][j][2], acc[i16][j][3],
                                 af[i16][0], af[i16][1], af[i16][2], af[i16][3],
                                 b0, b1);
                }
            }
            __syncthreads();
        }

#pragma unroll
        for (int i16 = 0; i16 < 2; ++i16) {
            int rA = row0 + warpM * 32 + i16 * 16 + g;
            int rB = rA + 8;
#pragma unroll
            for (int j = 0; j < NJ2; ++j) {
                int col = warpN * (HO2 / 2) + j * 8 + 2 * t;
                float2 bv = *reinterpret_cast<const float2*>(&b3v[col]);
                if (rA < n) {
                    float2 o;
                    o.x = acc[i16][j][0] + bv.x;
                    o.y = acc[i16][j][1] + bv.y;
                    if (RELU2) { o.x = fmaxf(o.x, 0.f); o.y = fmaxf(o.y, 0.f); }
                    *reinterpret_cast<float2*>(&C[rA * HO2 + col]) = o;
                }
                if (rB < n) {
                    float2 o;
                    o.x = acc[i16][j][2] + bv.x;
                    o.y = acc[i16][j][3] + bv.y;
                    if (RELU2) { o.x = fmaxf(o.x, 0.f); o.y = fmaxf(o.y, 0.f); }
                    *reinterpret_cast<float2*>(&C[rB * HO2 + col]) = o;
                }
            }
        }
    }
}

__global__ void __launch_bounds__(256, 2)
kfusedA(const float* __restrict__ xin,
        const float* __restrict__ b1, const float* __restrict__ blin1, int n) {
    fused_body<64, 64, 128, true>(s_agA, xin, w1l_tf, w1r_tf, b1, wl1_tf, blin1, s_t2, n);
}
__global__ void __launch_bounds__(256, 2)
kfusedB(const float* __restrict__ b2, const float* __restrict__ blin2,
        float* __restrict__ outp, int n) {
    fused_body<128, 128, 64, false>(s_agB, s_t2, w2l_tf, w2r_tf, b2, wl2_tf, blin2, outp, n);
}

// ---------------------------------------------------------------------------
// Launch. Inputs (metadata order): x, edge_index, W1l, b1, W1r, Wlin1, blin1,
//                                  W2l, b2, W2r, Wlin2, blin2
// ---------------------------------------------------------------------------
extern "C" void kernel_launch(void* const* d_in, const int* in_sizes, int n_in,
                              void* d_out, int out_size) {
    const float* xin   = (const float*)d_in[0];
    const int*   eidx  = (const int*)d_in[1];
    const float* W1l   = (const float*)d_in[2];
    const float* b1    = (const float*)d_in[3];
    const float* W1r   = (const float*)d_in[4];
    const float* Wlin1 = (const float*)d_in[5];
    const float* blin1 = (const float*)d_in[6];
    const float* W2l   = (const float*)d_in[7];
    const float* b2    = (const float*)d_in[8];
    const float* W2r   = (const float*)d_in[9];
    const float* Wlin2 = (const float*)d_in[10];
    const float* blin2 = (const float*)d_in[11];
    float*       outp  = (float*)d_out;

    const int n = in_sizes[0] / P_D;   // 100000
    const int E = in_sizes[1] / 2;     // 1600000

    const int SMEM_BYTES = (128 * 132 + 2 * 128 * 20 + 2 * 16 * 136) * 4;
    cudaFuncSetAttribute(kfusedA, cudaFuncAttributeMaxDynamicSharedMemorySize, SMEM_BYTES);
    cudaFuncSetAttribute(kfusedB, cudaFuncAttributeMaxDynamicSharedMemorySize, SMEM_BYTES);

    // Weight pre-conversion + CSR build (parallel scan)
    kconv_w<<<64, 256>>>(W1l, W1r, Wlin1, W2l, W2r, Wlin2);
    kcsr_zero<<<(P_N + 256) / 256, 256>>>();
    kcsr_hist<<<(E + 255) / 256, 256>>>(eidx, E);
    kscan1<<<SCAN_NB, SCAN_BLK>>>();
    kscan2<<<1, 128>>>();
    kscan3<<<SCAN_NB, SCAN_BLK>>>(E);
    kcsr_fill<<<(E + 255) / 256, 256>>>(eidx, E);

    const int nblk  = (n + 127) / 128;
    const int nblkG = (n + 7) / 8;

    // Layer block 1: gather + fused (sage1 + lin1)
    kg_one<<<nblkG, 256>>>(reinterpret_cast<const float2*>(xin));
    kfusedA<<<nblk, 256, SMEM_BYTES>>>(xin, b1, blin1, n);

    // Layer block 2: gather + fused (sage2 + lin2)
    kg_two<<<nblkG, 256>>>(0);
    kfusedB<<<nblk, 256, SMEM_BYTES>>>(b2, blin2, outp, n);
}